// round 7
// baseline (speedup 1.0000x reference)
#include <cuda_runtime.h>
#include <cuda_bf16.h>
#include <math.h>
#include <stdint.h>

#define TT    2048
#define BB    2
#define DIMM  2048
#define HEADS 16
#define HD    128
#define INNER 2048
#define NQKV  6144
#define MROWS 4096   // B*T

// ---------------------------------------------------------------------------
// Scratch (device globals; no allocations allowed)
// ---------------------------------------------------------------------------
__device__ float g_qkv[(size_t)MROWS * NQKV];   // [4096, 6144] q|k|v
__device__ float g_attn[(size_t)MROWS * INNER]; // [4096, 2048]
__device__ float g_cos[TT * 64];
__device__ float g_sin[TT * 64];
// bf16x3 operand buffers
__device__ __nv_bfloat16 gA_hi[(size_t)MROWS * DIMM];
__device__ __nv_bfloat16 gA_lo[(size_t)MROWS * DIMM];
__device__ __nv_bfloat16 gB_hi[(size_t)NQKV * DIMM];   // [N,K] transposed
__device__ __nv_bfloat16 gB_lo[(size_t)NQKV * DIMM];

// ---------------------------------------------------------------------------
// Portable PTX helpers (sm_80+): cp.async + mma.sync bf16
// ---------------------------------------------------------------------------
__device__ __forceinline__ uint32_t smem_u32(const void* p) {
    uint32_t a;
    asm("{ .reg .u64 t; cvta.to.shared.u64 t, %1; cvt.u32.u64 %0, t; }"
        : "=r"(a) : "l"(p));
    return a;
}
__device__ __forceinline__ void cp16(uint32_t saddr, const void* g) {
    asm volatile("cp.async.ca.shared.global [%0], [%1], 16;"
                 :: "r"(saddr), "l"(g) : "memory");
}
#define CP_COMMIT() asm volatile("cp.async.commit_group;" ::: "memory")
#define CP_WAIT0()  asm volatile("cp.async.wait_group 0;" ::: "memory")
#define CP_WAIT1()  asm volatile("cp.async.wait_group 1;" ::: "memory")

__device__ __forceinline__ void mma16816(float* c, const uint32_t* a,
                                         const uint32_t* b) {
    asm volatile(
        "mma.sync.aligned.m16n8k16.row.col.f32.bf16.bf16.f32 "
        "{%0,%1,%2,%3}, {%4,%5,%6,%7}, {%8,%9}, {%0,%1,%2,%3};"
        : "+f"(c[0]), "+f"(c[1]), "+f"(c[2]), "+f"(c[3])
        : "r"(a[0]), "r"(a[1]), "r"(a[2]), "r"(a[3]), "r"(b[0]), "r"(b[1]));
}

// ---------------------------------------------------------------------------
// RoPE cos/sin tables in fp64
// ---------------------------------------------------------------------------
__global__ void table_kernel() {
    int idx = blockIdx.x * 256 + threadIdx.x;
    int j = idx & 63;
    int t = idx >> 6;
    double inv = exp(-log(10000.0) * (double)j / 64.0);
    double ang = (double)t * inv;
    g_cos[idx] = (float)cos(ang);
    g_sin[idx] = (float)sin(ang);
}

// ---------------------------------------------------------------------------
// fp32 -> bf16 hi/lo split, same layout
// ---------------------------------------------------------------------------
__global__ __launch_bounds__(256) void conv_split(
    const float* __restrict__ src, __nv_bfloat16* __restrict__ hi,
    __nv_bfloat16* __restrict__ lo)
{
    int i = blockIdx.x * 256 + threadIdx.x;
    float4 v = ((const float4*)src)[i];
    float vv[4] = {v.x, v.y, v.z, v.w};
#pragma unroll
    for (int j = 0; j < 4; ++j) {
        __nv_bfloat16 h = __float2bfloat16(vv[j]);
        hi[i * 4 + j] = h;
        lo[i * 4 + j] = __float2bfloat16(vv[j] - __bfloat162float(h));
    }
}

// ---------------------------------------------------------------------------
// fp32 [K,N] -> transposed bf16 hi/lo [N,K]
// ---------------------------------------------------------------------------
__global__ __launch_bounds__(256) void conv_split_T(
    const float* __restrict__ src, __nv_bfloat16* __restrict__ hiT,
    __nv_bfloat16* __restrict__ loT, int K, int N)
{
    __shared__ float tile[32][33];
    int n0 = blockIdx.x * 32, k0 = blockIdx.y * 32;
    int tx = threadIdx.x, ty = threadIdx.y;
#pragma unroll
    for (int j = 0; j < 4; ++j)
        tile[ty + 8 * j][tx] = src[(size_t)(k0 + ty + 8 * j) * N + n0 + tx];
    __syncthreads();
#pragma unroll
    for (int j = 0; j < 4; ++j) {
        float v = tile[tx][ty + 8 * j];
        __nv_bfloat16 h = __float2bfloat16(v);
        size_t o = (size_t)(n0 + ty + 8 * j) * K + k0 + tx;
        hiT[o] = h;
        loT[o] = __float2bfloat16(v - __bfloat162float(h));
    }
}

// ---------------------------------------------------------------------------
// mma.sync bf16x3 GEMM.  C[M,N] = A[M,K] @ B[K,N] in ~fp32 precision.
// A: hi/lo bf16 [M,K].  B: hi/lo bf16 TRANSPOSED [N,K].
// CTA: 128x128 tile, 256 threads = 8 warps (2 M x 4 N), warp tile 64x32.
// K-chunks of 32, cp.async double buffer. smem rows padded to 80B.
// Fragment loads use GENERIC pointers into the shared array (LDS), while
// cp.async uses the cvta.to.shared u32 addresses.
// ---------------------------------------------------------------------------
#define KC       32
#define ROWB     80                   // bytes per 32-bf16 row (conflict-free)
#define TILE_B   (128 * ROWB)         // 10240
#define OFF_AH   0
#define OFF_AL   TILE_B
#define OFF_BH   (2 * TILE_B)
#define OFF_BL   (3 * TILE_B)
#define STAGE_B  (4 * TILE_B)         // 40960
#define GEMM_SMEM (2 * STAGE_B)       // 81920

__device__ __forceinline__ void load_chunk(
    uint32_t sbase,
    const __nv_bfloat16* __restrict__ Ah, const __nv_bfloat16* __restrict__ Al,
    const __nv_bfloat16* __restrict__ Bh, const __nv_bfloat16* __restrict__ Bl,
    int bm, int bn, int kc, int Kd, int tid)
{
    const int r  = tid >> 1;            // 0..127
    const int s0 = (tid & 1) * 2;       // 0 or 2  (16B units within 64B row)
    const size_t ga = (size_t)(bm + r) * Kd + kc * KC;
    const size_t gb = (size_t)(bn + r) * Kd + kc * KC;
    const uint32_t srow = sbase + r * ROWB;
#pragma unroll
    for (int s = s0; s < s0 + 2; ++s) {
        cp16(srow + OFF_AH + s * 16, Ah + ga + s * 8);
        cp16(srow + OFF_AL + s * 16, Al + ga + s * 8);
        cp16(srow + OFF_BH + s * 16, Bh + gb + s * 8);
        cp16(srow + OFF_BL + s * 16, Bl + gb + s * 8);
    }
}

__global__ __launch_bounds__(256, 1) void gemm_bf16x3(
    const __nv_bfloat16* __restrict__ Ah, const __nv_bfloat16* __restrict__ Al,
    const __nv_bfloat16* __restrict__ Bh, const __nv_bfloat16* __restrict__ Bl,
    float* __restrict__ C, int Kd, int Ncols)
{
    extern __shared__ char smem[];
    const uint32_t sb = smem_u32(smem);
    const int tid  = threadIdx.x;
    const int wid  = tid >> 5;
    const int lane = tid & 31;
    const int g    = lane >> 2;         // group id 0..7
    const int tig  = lane & 3;          // thread-in-group
    const int wm   = wid & 1;           // 0..1 -> M offset 64*wm
    const int wn   = wid >> 1;          // 0..3 -> N offset 32*wn
    const int bm   = blockIdx.y * 128;
    const int bn   = blockIdx.x * 128;

    float acc[4][4][4];
#pragma unroll
    for (int ms = 0; ms < 4; ++ms)
#pragma unroll
        for (int ns = 0; ns < 4; ++ns)
#pragma unroll
            for (int q = 0; q < 4; ++q) acc[ms][ns][q] = 0.0f;

    const int NT = Kd / KC;

    load_chunk(sb, Ah, Al, Bh, Bl, bm, bn, 0, Kd, tid);
    CP_COMMIT();

    for (int kc = 0; kc < NT; ++kc) {
        const int cur = kc & 1;
        if (kc + 1 < NT) {
            load_chunk(sb + (cur ^ 1) * STAGE_B, Ah, Al, Bh, Bl,
                       bm, bn, kc + 1, Kd, tid);
            CP_COMMIT();
            CP_WAIT1();
        } else {
            CP_WAIT0();
        }
        __syncthreads();

        const char* st = smem + cur * STAGE_B;   // generic pointer for LDS
#pragma unroll
        for (int kk = 0; kk < 2; ++kk) {
            const int kbyte = kk * 32 + tig * 4;   // k16 base + tig*2 elems

            uint32_t afh[4][4], afl[4][4];
#pragma unroll
            for (int ms = 0; ms < 4; ++ms) {
                const char* ar = st + (wm * 64 + ms * 16 + g) * ROWB + kbyte;
                afh[ms][0] = *(const uint32_t*)(ar + OFF_AH);
                afh[ms][1] = *(const uint32_t*)(ar + OFF_AH + 8 * ROWB);
                afh[ms][2] = *(const uint32_t*)(ar + OFF_AH + 16);
                afh[ms][3] = *(const uint32_t*)(ar + OFF_AH + 8 * ROWB + 16);
                afl[ms][0] = *(const uint32_t*)(ar + OFF_AL);
                afl[ms][1] = *(const uint32_t*)(ar + OFF_AL + 8 * ROWB);
                afl[ms][2] = *(const uint32_t*)(ar + OFF_AL + 16);
                afl[ms][3] = *(const uint32_t*)(ar + OFF_AL + 8 * ROWB + 16);
            }
            uint32_t bfh[4][2], bfl[4][2];
#pragma unroll
            for (int ns = 0; ns < 4; ++ns) {
                const char* br = st + (wn * 32 + ns * 8 + g) * ROWB + kbyte;
                bfh[ns][0] = *(const uint32_t*)(br + OFF_BH);
                bfh[ns][1] = *(const uint32_t*)(br + OFF_BH + 16);
                bfl[ns][0] = *(const uint32_t*)(br + OFF_BL);
                bfl[ns][1] = *(const uint32_t*)(br + OFF_BL + 16);
            }
#pragma unroll
            for (int ms = 0; ms < 4; ++ms)
#pragma unroll
                for (int ns = 0; ns < 4; ++ns) {
                    mma16816(acc[ms][ns], afh[ms], bfh[ns]);
                    mma16816(acc[ms][ns], afh[ms], bfl[ns]);
                    mma16816(acc[ms][ns], afl[ms], bfh[ns]);
                }
        }
        __syncthreads();
    }

    // Epilogue: C fragment (row g / g+8, cols 2tig,2tig+1) per 16x8 sub-tile
#pragma unroll
    for (int ms = 0; ms < 4; ++ms) {
        const int row = bm + wm * 64 + ms * 16 + g;
#pragma unroll
        for (int ns = 0; ns < 4; ++ns) {
            const int col = bn + wn * 32 + ns * 8 + tig * 2;
            *(float2*)&C[(size_t)row * Ncols + col] =
                make_float2(acc[ms][ns][0], acc[ms][ns][1]);
            *(float2*)&C[(size_t)(row + 8) * Ncols + col] =
                make_float2(acc[ms][ns][2], acc[ms][ns][3]);
        }
    }
}

// ---------------------------------------------------------------------------
// RoPE in place on q and k sections (tables)
// ---------------------------------------------------------------------------
__global__ __launch_bounds__(256) void rope_kernel(float* __restrict__ qkv)
{
    int idx = blockIdx.x * 256 + threadIdx.x;   // < 4194304
    int j = idx & 63;
    int h = (idx >> 6) & 15;
    int m = idx >> 10;
    int t = m & (TT - 1);

    float c = g_cos[t * 64 + j];
    float s = g_sin[t * 64 + j];

    size_t base = (size_t)m * NQKV + h * HD + j;
    float q1 = qkv[base];
    float q2 = qkv[base + 64];
    qkv[base]      = q1 * c - q2 * s;
    qkv[base + 64] = q2 * c + q1 * s;

    size_t kb = base + INNER;
    float k1 = qkv[kb];
    float k2 = qkv[kb + 64];
    qkv[kb]      = k1 * c - k2 * s;
    qkv[kb + 64] = k2 * c + k1 * s;
}

// ---------------------------------------------------------------------------
// Causal attention, one warp per query row (known-good)
// ---------------------------------------------------------------------------
__global__ __launch_bounds__(128) void attn_kernel(
    const float* __restrict__ qkv, float* __restrict__ outb)
{
    const int lane = threadIdx.x & 31;
    const int w    = threadIdx.x >> 5;
    const int b    = blockIdx.y >> 4;
    const int h    = blockIdx.y & 15;
    const int r    = TT - 1 - (blockIdx.x * 4 + w);

    const float scale = 0.08838834764831845f;

    const float* qrow = qkv + (size_t)(b * TT + r) * NQKV + h * HD;
    float q0 = qrow[lane]      * scale;
    float q1 = qrow[lane + 32] * scale;
    float q2 = qrow[lane + 64] * scale;
    float q3 = qrow[lane + 96] * scale;

    float m_i = -1.0e30f;
    float l_i = 0.0f;
    float o0 = 0.0f, o1 = 0.0f, o2 = 0.0f, o3 = 0.0f;

    const float* kbase = qkv + (size_t)(b * TT) * NQKV + INNER     + h * HD;
    const float* vbase = qkv + (size_t)(b * TT) * NQKV + 2 * INNER + h * HD;

    for (int k = 0; k <= r; ++k) {
        const float* kr = kbase + (size_t)k * NQKV;
        float part = q0 * kr[lane]
                   + q1 * kr[lane + 32]
                   + q2 * kr[lane + 64]
                   + q3 * kr[lane + 96];
        part += __shfl_xor_sync(0xffffffffu, part, 1);
        part += __shfl_xor_sync(0xffffffffu, part, 2);
        part += __shfl_xor_sync(0xffffffffu, part, 4);
        part += __shfl_xor_sync(0xffffffffu, part, 8);
        part += __shfl_xor_sync(0xffffffffu, part, 16);
        float s = part;

        float mn    = fmaxf(m_i, s);
        float alpha = expf(m_i - mn);
        float p     = expf(s - mn);
        m_i = mn;
        l_i = l_i * alpha + p;

        const float* vr = vbase + (size_t)k * NQKV;
        o0 = o0 * alpha + p * vr[lane];
        o1 = o1 * alpha + p * vr[lane + 32];
        o2 = o2 * alpha + p * vr[lane + 64];
        o3 = o3 * alpha + p * vr[lane + 96];
    }

    float inv = 1.0f / l_i;
    float* orow = outb + (size_t)(b * TT + r) * INNER + h * HD;
    orow[lane]      = o0 * inv;
    orow[lane + 32] = o1 * inv;
    orow[lane + 64] = o2 * inv;
    orow[lane + 96] = o3 * inv;
}

// ---------------------------------------------------------------------------
// Entry point
// ---------------------------------------------------------------------------
extern "C" void kernel_launch(void* const* d_in, const int* in_sizes, int n_in,
                              void* d_out, int out_size)
{
    (void)out_size;
    const int NX = BB * TT * DIMM;   // 8388608
    const int NW = DIMM * NQKV;      // 12582912
    const int NO = INNER * DIMM;     // 4194304

    const float* x     = nullptr;
    const float* w_qkv = nullptr;
    const float* w_out = nullptr;
    for (int i = 0; i < n_in; ++i) {
        int sz = in_sizes[i];
        if      (sz == NX || sz == NX * 4) x     = (const float*)d_in[i];
        else if (sz == NW || sz == NW * 4) w_qkv = (const float*)d_in[i];
        else if (sz == NO || sz == NO * 4) w_out = (const float*)d_in[i];
    }
    if (!x || !w_qkv || !w_out) {
        x     = (const float*)d_in[0];
        w_qkv = (const float*)d_in[1];
        w_out = (const float*)d_in[2];
    }

    float* out = (float*)d_out;

    float *qkv_p, *attn_p;
    __nv_bfloat16 *ah, *al, *bh, *bl;
    cudaGetSymbolAddress((void**)&qkv_p,  g_qkv);
    cudaGetSymbolAddress((void**)&attn_p, g_attn);
    cudaGetSymbolAddress((void**)&ah, gA_hi);
    cudaGetSymbolAddress((void**)&al, gA_lo);
    cudaGetSymbolAddress((void**)&bh, gB_hi);
    cudaGetSymbolAddress((void**)&bl, gB_lo);

    cudaFuncSetAttribute(gemm_bf16x3,
                         cudaFuncAttributeMaxDynamicSharedMemorySize, GEMM_SMEM);

    // 1. RoPE tables
    table_kernel<<<(TT * 64) / 256, 256>>>();

    // 2. Split x -> bf16 hi/lo; transpose-split w_qkv
    conv_split<<<NX / 1024, 256>>>(x, ah, al);
    conv_split_T<<<dim3(NQKV / 32, DIMM / 32), dim3(32, 8)>>>(w_qkv, bh, bl,
                                                              DIMM, NQKV);
    // 3. QKV projection on tensor cores (mma.sync)
    gemm_bf16x3<<<dim3(NQKV / 128, MROWS / 128), 256, GEMM_SMEM>>>(
        ah, al, bh, bl, qkv_p, DIMM, NQKV);

    // 4. RoPE in place
    rope_kernel<<<(MROWS * HEADS * 64) / 256, 256>>>(qkv_p);

    // 5. Causal attention
    attn_kernel<<<dim3(TT / 4, BB * HEADS), 128>>>(qkv_p, attn_p);

    // 6. Split attn output + transpose-split w_out; out projection
    conv_split<<<(MROWS * INNER) / 1024, 256>>>(attn_p, ah, al);
    conv_split_T<<<dim3(DIMM / 32, INNER / 32), dim3(32, 8)>>>(w_out, bh, bl,
                                                               INNER, DIMM);
    gemm_bf16x3<<<dim3(DIMM / 128, MROWS / 128), 256, GEMM_SMEM>>>(
        ah, al, bh, bl, out, INNER, DIMM);
}

// round 8
// speedup vs baseline: 1.8115x; 1.8115x over previous
#include <cuda_runtime.h>
#include <cuda_bf16.h>
#include <math.h>
#include <stdint.h>

#define TT    2048
#define BB    2
#define DIMM  2048
#define HEADS 16
#define HD    128
#define INNER 2048
#define NQKV  6144
#define MROWS 4096   // B*T

// ---------------------------------------------------------------------------
// Scratch (device globals; no allocations allowed)
// ---------------------------------------------------------------------------
__device__ float g_qkv[(size_t)MROWS * NQKV];   // [4096, 6144] q|k|v
__device__ float g_attn[(size_t)MROWS * INNER]; // [4096, 2048]
__device__ float g_cos[TT * 64];
__device__ float g_sin[TT * 64];
// bf16x3 operand buffers
__device__ __nv_bfloat16 gA_hi[(size_t)MROWS * DIMM];
__device__ __nv_bfloat16 gA_lo[(size_t)MROWS * DIMM];
__device__ __nv_bfloat16 gB_hi[(size_t)NQKV * DIMM];   // [N,K] transposed
__device__ __nv_bfloat16 gB_lo[(size_t)NQKV * DIMM];

// ---------------------------------------------------------------------------
// Portable PTX helpers (sm_80+): cp.async + mma.sync bf16
// ---------------------------------------------------------------------------
__device__ __forceinline__ uint32_t smem_u32(const void* p) {
    uint32_t a;
    asm("{ .reg .u64 t; cvta.to.shared.u64 t, %1; cvt.u32.u64 %0, t; }"
        : "=r"(a) : "l"(p));
    return a;
}
__device__ __forceinline__ void cp16(uint32_t saddr, const void* g) {
    asm volatile("cp.async.ca.shared.global [%0], [%1], 16;"
                 :: "r"(saddr), "l"(g) : "memory");
}
#define CP_COMMIT() asm volatile("cp.async.commit_group;" ::: "memory")
#define CP_WAIT0()  asm volatile("cp.async.wait_group 0;" ::: "memory")
#define CP_WAIT1()  asm volatile("cp.async.wait_group 1;" ::: "memory")

__device__ __forceinline__ void mma16816(float* c, const uint32_t* a,
                                         const uint32_t* b) {
    asm volatile(
        "mma.sync.aligned.m16n8k16.row.col.f32.bf16.bf16.f32 "
        "{%0,%1,%2,%3}, {%4,%5,%6,%7}, {%8,%9}, {%0,%1,%2,%3};"
        : "+f"(c[0]), "+f"(c[1]), "+f"(c[2]), "+f"(c[3])
        : "r"(a[0]), "r"(a[1]), "r"(a[2]), "r"(a[3]), "r"(b[0]), "r"(b[1]));
}

// ---------------------------------------------------------------------------
// RoPE cos/sin tables in fp64
// ---------------------------------------------------------------------------
__global__ void table_kernel() {
    int idx = blockIdx.x * 256 + threadIdx.x;
    int j = idx & 63;
    int t = idx >> 6;
    double inv = exp(-log(10000.0) * (double)j / 64.0);
    double ang = (double)t * inv;
    g_cos[idx] = (float)cos(ang);
    g_sin[idx] = (float)sin(ang);
}

// ---------------------------------------------------------------------------
// fp32 -> bf16 hi/lo split, same layout
// ---------------------------------------------------------------------------
__global__ __launch_bounds__(256) void conv_split(
    const float* __restrict__ src, __nv_bfloat16* __restrict__ hi,
    __nv_bfloat16* __restrict__ lo)
{
    int i = blockIdx.x * 256 + threadIdx.x;
    float4 v = ((const float4*)src)[i];
    float vv[4] = {v.x, v.y, v.z, v.w};
#pragma unroll
    for (int j = 0; j < 4; ++j) {
        __nv_bfloat16 h = __float2bfloat16(vv[j]);
        hi[i * 4 + j] = h;
        lo[i * 4 + j] = __float2bfloat16(vv[j] - __bfloat162float(h));
    }
}

// ---------------------------------------------------------------------------
// fp32 [K,N] -> transposed bf16 hi/lo [N,K]
// ---------------------------------------------------------------------------
__global__ __launch_bounds__(256) void conv_split_T(
    const float* __restrict__ src, __nv_bfloat16* __restrict__ hiT,
    __nv_bfloat16* __restrict__ loT, int K, int N)
{
    __shared__ float tile[32][33];
    int n0 = blockIdx.x * 32, k0 = blockIdx.y * 32;
    int tx = threadIdx.x, ty = threadIdx.y;
#pragma unroll
    for (int j = 0; j < 4; ++j)
        tile[ty + 8 * j][tx] = src[(size_t)(k0 + ty + 8 * j) * N + n0 + tx];
    __syncthreads();
#pragma unroll
    for (int j = 0; j < 4; ++j) {
        float v = tile[tx][ty + 8 * j];
        __nv_bfloat16 h = __float2bfloat16(v);
        size_t o = (size_t)(n0 + ty + 8 * j) * K + k0 + tx;
        hiT[o] = h;
        loT[o] = __float2bfloat16(v - __bfloat162float(h));
    }
}

// ---------------------------------------------------------------------------
// mma.sync bf16x3 GEMM.  C[M,N] = A[M,K] @ B[K,N] in ~fp32 precision.
// CTA: 128x128 tile, 512 threads = 16 warps (4 M x 4 N), warp tile 32x32.
// K-chunks of 32, cp.async double buffer, smem rows padded to 80B.
// ---------------------------------------------------------------------------
#define KC       32
#define ROWB     80
#define TILE_B   (128 * ROWB)         // 10240
#define OFF_AH   0
#define OFF_AL   TILE_B
#define OFF_BH   (2 * TILE_B)
#define OFF_BL   (3 * TILE_B)
#define STAGE_B  (4 * TILE_B)         // 40960
#define GEMM_SMEM (2 * STAGE_B)       // 81920

__device__ __forceinline__ void load_chunk(
    uint32_t sbase,
    const __nv_bfloat16* __restrict__ Ah, const __nv_bfloat16* __restrict__ Al,
    const __nv_bfloat16* __restrict__ Bh, const __nv_bfloat16* __restrict__ Bl,
    int bm, int bn, int kc, int Kd, int tid)
{
    const int r = tid >> 2;             // 0..127
    const int s = tid & 3;              // 16B segment within 64B row
    const size_t ga = (size_t)(bm + r) * Kd + kc * KC + s * 8;
    const size_t gb = (size_t)(bn + r) * Kd + kc * KC + s * 8;
    const uint32_t srow = sbase + r * ROWB + s * 16;
    cp16(srow + OFF_AH, Ah + ga);
    cp16(srow + OFF_AL, Al + ga);
    cp16(srow + OFF_BH, Bh + gb);
    cp16(srow + OFF_BL, Bl + gb);
}

__global__ __launch_bounds__(512, 1) void gemm_bf16x3(
    const __nv_bfloat16* __restrict__ Ah, const __nv_bfloat16* __restrict__ Al,
    const __nv_bfloat16* __restrict__ Bh, const __nv_bfloat16* __restrict__ Bl,
    float* __restrict__ C, int Kd, int Ncols)
{
    extern __shared__ char smem[];
    const uint32_t sb = smem_u32(smem);
    const int tid  = threadIdx.x;
    const int wid  = tid >> 5;
    const int lane = tid & 31;
    const int g    = lane >> 2;
    const int tig  = lane & 3;
    const int wm   = wid & 3;           // M offset 32*wm
    const int wn   = wid >> 2;          // N offset 32*wn
    const int bm   = blockIdx.y * 128;
    const int bn   = blockIdx.x * 128;

    float acc[2][4][4];
#pragma unroll
    for (int ms = 0; ms < 2; ++ms)
#pragma unroll
        for (int ns = 0; ns < 4; ++ns)
#pragma unroll
            for (int q = 0; q < 4; ++q) acc[ms][ns][q] = 0.0f;

    const int NT = Kd / KC;

    load_chunk(sb, Ah, Al, Bh, Bl, bm, bn, 0, Kd, tid);
    CP_COMMIT();

    for (int kc = 0; kc < NT; ++kc) {
        const int cur = kc & 1;
        if (kc + 1 < NT) {
            load_chunk(sb + (cur ^ 1) * STAGE_B, Ah, Al, Bh, Bl,
                       bm, bn, kc + 1, Kd, tid);
            CP_COMMIT();
            CP_WAIT1();
        } else {
            CP_WAIT0();
        }
        __syncthreads();

        const char* st = smem + cur * STAGE_B;
#pragma unroll
        for (int kk = 0; kk < 2; ++kk) {
            const int kbyte = kk * 32 + tig * 4;

            uint32_t afh[2][4], afl[2][4];
#pragma unroll
            for (int ms = 0; ms < 2; ++ms) {
                const char* ar = st + (wm * 32 + ms * 16 + g) * ROWB + kbyte;
                afh[ms][0] = *(const uint32_t*)(ar + OFF_AH);
                afh[ms][1] = *(const uint32_t*)(ar + OFF_AH + 8 * ROWB);
                afh[ms][2] = *(const uint32_t*)(ar + OFF_AH + 16);
                afh[ms][3] = *(const uint32_t*)(ar + OFF_AH + 8 * ROWB + 16);
                afl[ms][0] = *(const uint32_t*)(ar + OFF_AL);
                afl[ms][1] = *(const uint32_t*)(ar + OFF_AL + 8 * ROWB);
                afl[ms][2] = *(const uint32_t*)(ar + OFF_AL + 16);
                afl[ms][3] = *(const uint32_t*)(ar + OFF_AL + 8 * ROWB + 16);
            }
            uint32_t bfh[4][2], bfl[4][2];
#pragma unroll
            for (int ns = 0; ns < 4; ++ns) {
                const char* br = st + (wn * 32 + ns * 8 + g) * ROWB + kbyte;
                bfh[ns][0] = *(const uint32_t*)(br + OFF_BH);
                bfh[ns][1] = *(const uint32_t*)(br + OFF_BH + 16);
                bfl[ns][0] = *(const uint32_t*)(br + OFF_BL);
                bfl[ns][1] = *(const uint32_t*)(br + OFF_BL + 16);
            }
#pragma unroll
            for (int ms = 0; ms < 2; ++ms)
#pragma unroll
                for (int ns = 0; ns < 4; ++ns) {
                    mma16816(acc[ms][ns], afh[ms], bfh[ns]);
                    mma16816(acc[ms][ns], afh[ms], bfl[ns]);
                    mma16816(acc[ms][ns], afl[ms], bfh[ns]);
                }
        }
        __syncthreads();
    }

    // Epilogue
#pragma unroll
    for (int ms = 0; ms < 2; ++ms) {
        const int row = bm + wm * 32 + ms * 16 + g;
#pragma unroll
        for (int ns = 0; ns < 4; ++ns) {
            const int col = bn + wn * 32 + ns * 8 + tig * 2;
            *(float2*)&C[(size_t)row * Ncols + col] =
                make_float2(acc[ms][ns][0], acc[ms][ns][1]);
            *(float2*)&C[(size_t)(row + 8) * Ncols + col] =
                make_float2(acc[ms][ns][2], acc[ms][ns][3]);
        }
    }
}

// ---------------------------------------------------------------------------
// RoPE in place on q and k sections (tables)
// ---------------------------------------------------------------------------
__global__ __launch_bounds__(256) void rope_kernel(float* __restrict__ qkv)
{
    int idx = blockIdx.x * 256 + threadIdx.x;   // < 4194304
    int j = idx & 63;
    int h = (idx >> 6) & 15;
    int m = idx >> 10;
    int t = m & (TT - 1);

    float c = g_cos[t * 64 + j];
    float s = g_sin[t * 64 + j];

    size_t base = (size_t)m * NQKV + h * HD + j;
    float q1 = qkv[base];
    float q2 = qkv[base + 64];
    qkv[base]      = q1 * c - q2 * s;
    qkv[base + 64] = q2 * c + q1 * s;

    size_t kb = base + INNER;
    float k1 = qkv[kb];
    float k2 = qkv[kb + 64];
    qkv[kb]      = k1 * c - k2 * s;
    qkv[kb + 64] = k2 * c + k1 * s;
}

// ---------------------------------------------------------------------------
// Causal attention: one warp handles 4 query rows (r0-3..r0), sharing each
// K/V row load. float4 global accesses (lane owns dims 4*lane..4*lane+3).
// Online softmax per row; full-warp reductions give warp-uniform state.
// ---------------------------------------------------------------------------
__global__ __launch_bounds__(128) void attn_kernel(
    const float* __restrict__ qkv, float* __restrict__ outb)
{
    const int lane = threadIdx.x & 31;
    const int w    = threadIdx.x >> 5;
    const int b    = blockIdx.y >> 4;
    const int h    = blockIdx.y & 15;
    const int r0   = TT - 1 - (blockIdx.x * 16 + w * 4);   // heavy first; r0>=3

    const float scale = 0.08838834764831845f;   // 1/sqrt(128)

    float4 q[4];
#pragma unroll
    for (int i = 0; i < 4; ++i) {
        const float* qr = qkv + (size_t)(b * TT + r0 - i) * NQKV + h * HD;
        float4 v = *(const float4*)(qr + lane * 4);
        v.x *= scale; v.y *= scale; v.z *= scale; v.w *= scale;
        q[i] = v;
    }

    float m_i[4], l_i[4];
    float4 o[4];
#pragma unroll
    for (int i = 0; i < 4; ++i) {
        m_i[i] = -1.0e30f; l_i[i] = 0.0f;
        o[i] = make_float4(0.f, 0.f, 0.f, 0.f);
    }

    const float* kbase = qkv + (size_t)(b * TT) * NQKV + INNER     + h * HD;
    const float* vbase = qkv + (size_t)(b * TT) * NQKV + 2 * INNER + h * HD;

    for (int k = 0; k <= r0; ++k) {
        const float4 kv = *(const float4*)(kbase + (size_t)k * NQKV + lane * 4);
        const float4 vv = *(const float4*)(vbase + (size_t)k * NQKV + lane * 4);

        float s[4];
#pragma unroll
        for (int i = 0; i < 4; ++i) {
            float part = q[i].x * kv.x + q[i].y * kv.y
                       + q[i].z * kv.z + q[i].w * kv.w;
            part += __shfl_xor_sync(0xffffffffu, part, 1);
            part += __shfl_xor_sync(0xffffffffu, part, 2);
            part += __shfl_xor_sync(0xffffffffu, part, 4);
            part += __shfl_xor_sync(0xffffffffu, part, 8);
            part += __shfl_xor_sync(0xffffffffu, part, 16);
            s[i] = part;
        }
#pragma unroll
        for (int i = 0; i < 4; ++i) {
            if (k <= r0 - i) {
                float mn    = fmaxf(m_i[i], s[i]);
                float alpha = expf(m_i[i] - mn);
                float p     = expf(s[i] - mn);
                m_i[i] = mn;
                l_i[i] = l_i[i] * alpha + p;
                o[i].x = o[i].x * alpha + p * vv.x;
                o[i].y = o[i].y * alpha + p * vv.y;
                o[i].z = o[i].z * alpha + p * vv.z;
                o[i].w = o[i].w * alpha + p * vv.w;
            }
        }
    }

#pragma unroll
    for (int i = 0; i < 4; ++i) {
        float inv = 1.0f / l_i[i];
        float* orow = outb + (size_t)(b * TT + r0 - i) * INNER + h * HD;
        float4 v = make_float4(o[i].x * inv, o[i].y * inv,
                               o[i].z * inv, o[i].w * inv);
        *(float4*)(orow + lane * 4) = v;
    }
}

// ---------------------------------------------------------------------------
// Entry point
// ---------------------------------------------------------------------------
extern "C" void kernel_launch(void* const* d_in, const int* in_sizes, int n_in,
                              void* d_out, int out_size)
{
    (void)out_size;
    const int NX = BB * TT * DIMM;   // 8388608
    const int NW = DIMM * NQKV;      // 12582912
    const int NO = INNER * DIMM;     // 4194304

    const float* x     = nullptr;
    const float* w_qkv = nullptr;
    const float* w_out = nullptr;
    for (int i = 0; i < n_in; ++i) {
        int sz = in_sizes[i];
        if      (sz == NX || sz == NX * 4) x     = (const float*)d_in[i];
        else if (sz == NW || sz == NW * 4) w_qkv = (const float*)d_in[i];
        else if (sz == NO || sz == NO * 4) w_out = (const float*)d_in[i];
    }
    if (!x || !w_qkv || !w_out) {
        x     = (const float*)d_in[0];
        w_qkv = (const float*)d_in[1];
        w_out = (const float*)d_in[2];
    }

    float* out = (float*)d_out;

    float *qkv_p, *attn_p;
    __nv_bfloat16 *ah, *al, *bh, *bl;
    cudaGetSymbolAddress((void**)&qkv_p,  g_qkv);
    cudaGetSymbolAddress((void**)&attn_p, g_attn);
    cudaGetSymbolAddress((void**)&ah, gA_hi);
    cudaGetSymbolAddress((void**)&al, gA_lo);
    cudaGetSymbolAddress((void**)&bh, gB_hi);
    cudaGetSymbolAddress((void**)&bl, gB_lo);

    cudaFuncSetAttribute(gemm_bf16x3,
                         cudaFuncAttributeMaxDynamicSharedMemorySize, GEMM_SMEM);

    // 1. RoPE tables
    table_kernel<<<(TT * 64) / 256, 256>>>();

    // 2. Split x -> bf16 hi/lo; transpose-split w_qkv
    conv_split<<<NX / 1024, 256>>>(x, ah, al);
    conv_split_T<<<dim3(NQKV / 32, DIMM / 32), dim3(32, 8)>>>(w_qkv, bh, bl,
                                                              DIMM, NQKV);
    // 3. QKV projection (mma.sync, 16 warps/CTA)
    gemm_bf16x3<<<dim3(NQKV / 128, MROWS / 128), 512, GEMM_SMEM>>>(
        ah, al, bh, bl, qkv_p, DIMM, NQKV);

    // 4. RoPE in place
    rope_kernel<<<(MROWS * HEADS * 64) / 256, 256>>>(qkv_p);

    // 5. Causal attention (4 rows per warp)
    attn_kernel<<<dim3(TT / 16, BB * HEADS), 128>>>(qkv_p, attn_p);

    // 6. Split attn output + transpose-split w_out; out projection
    conv_split<<<(MROWS * INNER) / 1024, 256>>>(attn_p, ah, al);
    conv_split_T<<<dim3(DIMM / 32, INNER / 32), dim3(32, 8)>>>(w_out, bh, bl,
                                                               INNER, DIMM);
    gemm_bf16x3<<<dim3(DIMM / 128, MROWS / 128), 512, GEMM_SMEM>>>(
        ah, al, bh, bl, out, INNER, DIMM);
}

// round 9
// speedup vs baseline: 2.0140x; 1.1118x over previous
#include <cuda_runtime.h>
#include <cuda_bf16.h>
#include <math.h>
#include <stdint.h>

#define TT    2048
#define BB    2
#define DIMM  2048
#define HEADS 16
#define HD    128
#define INNER 2048
#define NQKV  6144
#define MROWS 4096   // B*T

// ---------------------------------------------------------------------------
// Scratch (device globals; no allocations allowed)
// ---------------------------------------------------------------------------
__device__ float g_qkv[(size_t)MROWS * NQKV];   // [4096, 6144] q|k|v
__device__ float g_attn[(size_t)MROWS * INNER]; // [4096, 2048]
__device__ float g_cos[TT * 64];
__device__ float g_sin[TT * 64];
// bf16x3 operand buffers
__device__ __nv_bfloat16 gA_hi[(size_t)MROWS * DIMM];
__device__ __nv_bfloat16 gA_lo[(size_t)MROWS * DIMM];
__device__ __nv_bfloat16 gB_hi[(size_t)NQKV * DIMM];   // [N,K] transposed
__device__ __nv_bfloat16 gB_lo[(size_t)NQKV * DIMM];

// ---------------------------------------------------------------------------
// Portable PTX helpers (sm_80+): cp.async + mma.sync bf16
// ---------------------------------------------------------------------------
__device__ __forceinline__ uint32_t smem_u32(const void* p) {
    uint32_t a;
    asm("{ .reg .u64 t; cvta.to.shared.u64 t, %1; cvt.u32.u64 %0, t; }"
        : "=r"(a) : "l"(p));
    return a;
}
__device__ __forceinline__ void cp16(uint32_t saddr, const void* g) {
    asm volatile("cp.async.ca.shared.global [%0], [%1], 16;"
                 :: "r"(saddr), "l"(g) : "memory");
}
#define CP_COMMIT() asm volatile("cp.async.commit_group;" ::: "memory")
#define CP_WAIT0()  asm volatile("cp.async.wait_group 0;" ::: "memory")
#define CP_WAIT1()  asm volatile("cp.async.wait_group 1;" ::: "memory")

__device__ __forceinline__ void mma16816(float* c, const uint32_t* a,
                                         const uint32_t* b) {
    asm volatile(
        "mma.sync.aligned.m16n8k16.row.col.f32.bf16.bf16.f32 "
        "{%0,%1,%2,%3}, {%4,%5,%6,%7}, {%8,%9}, {%0,%1,%2,%3};"
        : "+f"(c[0]), "+f"(c[1]), "+f"(c[2]), "+f"(c[3])
        : "r"(a[0]), "r"(a[1]), "r"(a[2]), "r"(a[3]), "r"(b[0]), "r"(b[1]));
}

// ---------------------------------------------------------------------------
// RoPE cos/sin tables in fp64
// ---------------------------------------------------------------------------
__global__ void table_kernel() {
    int idx = blockIdx.x * 256 + threadIdx.x;
    int j = idx & 63;
    int t = idx >> 6;
    double inv = exp(-log(10000.0) * (double)j / 64.0);
    double ang = (double)t * inv;
    g_cos[idx] = (float)cos(ang);
    g_sin[idx] = (float)sin(ang);
}

// ---------------------------------------------------------------------------
// fp32 -> bf16 hi/lo split, same layout
// ---------------------------------------------------------------------------
__global__ __launch_bounds__(256) void conv_split(
    const float* __restrict__ src, __nv_bfloat16* __restrict__ hi,
    __nv_bfloat16* __restrict__ lo)
{
    int i = blockIdx.x * 256 + threadIdx.x;
    float4 v = ((const float4*)src)[i];
    float vv[4] = {v.x, v.y, v.z, v.w};
#pragma unroll
    for (int j = 0; j < 4; ++j) {
        __nv_bfloat16 h = __float2bfloat16(vv[j]);
        hi[i * 4 + j] = h;
        lo[i * 4 + j] = __float2bfloat16(vv[j] - __bfloat162float(h));
    }
}

// ---------------------------------------------------------------------------
// fp32 [K,N] -> transposed bf16 hi/lo [N,K]
// ---------------------------------------------------------------------------
__global__ __launch_bounds__(256) void conv_split_T(
    const float* __restrict__ src, __nv_bfloat16* __restrict__ hiT,
    __nv_bfloat16* __restrict__ loT, int K, int N)
{
    __shared__ float tile[32][33];
    int n0 = blockIdx.x * 32, k0 = blockIdx.y * 32;
    int tx = threadIdx.x, ty = threadIdx.y;
#pragma unroll
    for (int j = 0; j < 4; ++j)
        tile[ty + 8 * j][tx] = src[(size_t)(k0 + ty + 8 * j) * N + n0 + tx];
    __syncthreads();
#pragma unroll
    for (int j = 0; j < 4; ++j) {
        float v = tile[tx][ty + 8 * j];
        __nv_bfloat16 h = __float2bfloat16(v);
        size_t o = (size_t)(n0 + ty + 8 * j) * K + k0 + tx;
        hiT[o] = h;
        loT[o] = __float2bfloat16(v - __bfloat162float(h));
    }
}

// ---------------------------------------------------------------------------
// mma.sync bf16x3 GEMM, 3-stage cp.async pipeline.
// CTA: 128x128 tile, 512 threads = 16 warps (4M x 4N), warp tile 32x32.
// ---------------------------------------------------------------------------
#define KC       32
#define ROWB     80
#define TILE_B   (128 * ROWB)         // 10240
#define OFF_AH   0
#define OFF_AL   TILE_B
#define OFF_BH   (2 * TILE_B)
#define OFF_BL   (3 * TILE_B)
#define STAGE_B  (4 * TILE_B)         // 40960
#define NSTAGE   3
#define GEMM_SMEM (NSTAGE * STAGE_B)  // 122880

__device__ __forceinline__ void load_chunk(
    uint32_t sbase,
    const __nv_bfloat16* __restrict__ Ah, const __nv_bfloat16* __restrict__ Al,
    const __nv_bfloat16* __restrict__ Bh, const __nv_bfloat16* __restrict__ Bl,
    int bm, int bn, int kc, int Kd, int tid)
{
    const int r = tid >> 2;             // 0..127
    const int s = tid & 3;              // 16B segment within 64B row
    const size_t ga = (size_t)(bm + r) * Kd + kc * KC + s * 8;
    const size_t gb = (size_t)(bn + r) * Kd + kc * KC + s * 8;
    const uint32_t srow = sbase + r * ROWB + s * 16;
    cp16(srow + OFF_AH, Ah + ga);
    cp16(srow + OFF_AL, Al + ga);
    cp16(srow + OFF_BH, Bh + gb);
    cp16(srow + OFF_BL, Bl + gb);
}

__global__ __launch_bounds__(512, 1) void gemm_bf16x3(
    const __nv_bfloat16* __restrict__ Ah, const __nv_bfloat16* __restrict__ Al,
    const __nv_bfloat16* __restrict__ Bh, const __nv_bfloat16* __restrict__ Bl,
    float* __restrict__ C, int Kd, int Ncols)
{
    extern __shared__ char smem[];
    const uint32_t sb = smem_u32(smem);
    const int tid  = threadIdx.x;
    const int wid  = tid >> 5;
    const int lane = tid & 31;
    const int g    = lane >> 2;
    const int tig  = lane & 3;
    const int wm   = wid & 3;           // M offset 32*wm
    const int wn   = wid >> 2;          // N offset 32*wn
    const int bm   = blockIdx.y * 128;
    const int bn   = blockIdx.x * 128;

    float acc[2][4][4];
#pragma unroll
    for (int ms = 0; ms < 2; ++ms)
#pragma unroll
        for (int ns = 0; ns < 4; ++ns)
#pragma unroll
            for (int q = 0; q < 4; ++q) acc[ms][ns][q] = 0.0f;

    const int NT = Kd / KC;

    load_chunk(sb, Ah, Al, Bh, Bl, bm, bn, 0, Kd, tid);
    CP_COMMIT();
    if (NT > 1) {
        load_chunk(sb + STAGE_B, Ah, Al, Bh, Bl, bm, bn, 1, Kd, tid);
        CP_COMMIT();
    }

    for (int kc = 0; kc < NT; ++kc) {
        if (kc + 1 < NT) { CP_WAIT1(); } else { CP_WAIT0(); }
        __syncthreads();
        if (kc + 2 < NT) {
            load_chunk(sb + ((kc + 2) % NSTAGE) * STAGE_B, Ah, Al, Bh, Bl,
                       bm, bn, kc + 2, Kd, tid);
            CP_COMMIT();
        }

        const char* st = smem + (kc % NSTAGE) * STAGE_B;
#pragma unroll
        for (int kk = 0; kk < 2; ++kk) {
            const int kbyte = kk * 32 + tig * 4;

            uint32_t afh[2][4], afl[2][4];
#pragma unroll
            for (int ms = 0; ms < 2; ++ms) {
                const char* ar = st + (wm * 32 + ms * 16 + g) * ROWB + kbyte;
                afh[ms][0] = *(const uint32_t*)(ar + OFF_AH);
                afh[ms][1] = *(const uint32_t*)(ar + OFF_AH + 8 * ROWB);
                afh[ms][2] = *(const uint32_t*)(ar + OFF_AH + 16);
                afh[ms][3] = *(const uint32_t*)(ar + OFF_AH + 8 * ROWB + 16);
                afl[ms][0] = *(const uint32_t*)(ar + OFF_AL);
                afl[ms][1] = *(const uint32_t*)(ar + OFF_AL + 8 * ROWB);
                afl[ms][2] = *(const uint32_t*)(ar + OFF_AL + 16);
                afl[ms][3] = *(const uint32_t*)(ar + OFF_AL + 8 * ROWB + 16);
            }
            uint32_t bfh[4][2], bfl[4][2];
#pragma unroll
            for (int ns = 0; ns < 4; ++ns) {
                const char* br = st + (wn * 32 + ns * 8 + g) * ROWB + kbyte;
                bfh[ns][0] = *(const uint32_t*)(br + OFF_BH);
                bfh[ns][1] = *(const uint32_t*)(br + OFF_BH + 16);
                bfl[ns][0] = *(const uint32_t*)(br + OFF_BL);
                bfl[ns][1] = *(const uint32_t*)(br + OFF_BL + 16);
            }
#pragma unroll
            for (int ms = 0; ms < 2; ++ms)
#pragma unroll
                for (int ns = 0; ns < 4; ++ns) {
                    mma16816(acc[ms][ns], afh[ms], bfh[ns]);
                    mma16816(acc[ms][ns], afh[ms], bfl[ns]);
                    mma16816(acc[ms][ns], afl[ms], bfh[ns]);
                }
        }
    }

    // Epilogue
#pragma unroll
    for (int ms = 0; ms < 2; ++ms) {
        const int row = bm + wm * 32 + ms * 16 + g;
#pragma unroll
        for (int ns = 0; ns < 4; ++ns) {
            const int col = bn + wn * 32 + ns * 8 + tig * 2;
            *(float2*)&C[(size_t)row * Ncols + col] =
                make_float2(acc[ms][ns][0], acc[ms][ns][1]);
            *(float2*)&C[(size_t)(row + 8) * Ncols + col] =
                make_float2(acc[ms][ns][2], acc[ms][ns][3]);
        }
    }
}

// ---------------------------------------------------------------------------
// RoPE in place on q and k sections (tables)
// ---------------------------------------------------------------------------
__global__ __launch_bounds__(256) void rope_kernel(float* __restrict__ qkv)
{
    int idx = blockIdx.x * 256 + threadIdx.x;   // < 4194304
    int j = idx & 63;
    int h = (idx >> 6) & 15;
    int m = idx >> 10;
    int t = m & (TT - 1);

    float c = g_cos[t * 64 + j];
    float s = g_sin[t * 64 + j];

    size_t base = (size_t)m * NQKV + h * HD + j;
    float q1 = qkv[base];
    float q2 = qkv[base + 64];
    qkv[base]      = q1 * c - q2 * s;
    qkv[base + 64] = q2 * c + q1 * s;

    size_t kb = base + INNER;
    float k1 = qkv[kb];
    float k2 = qkv[kb + 64];
    qkv[kb]      = k1 * c - k2 * s;
    qkv[kb + 64] = k2 * c + k1 * s;
}

// ---------------------------------------------------------------------------
// Causal flash attention, CTA-tiled.
// CTA = 16 q rows (4 warps x 4 rows), K/V staged in smem in 32-k blocks.
// Each lane owns one k-column for scores (reductions amortized over 32 k)
// and 4 output dims (4*lane..4*lane+3) for the PV accumulation.
// ---------------------------------------------------------------------------
#define AT_ROWS 16

__global__ __launch_bounds__(128) void attn_kernel(
    const float* __restrict__ qkv, float* __restrict__ outb)
{
    __shared__ float4 Qs4[32][AT_ROWS];   // [d4][r]       (broadcast reads)
    __shared__ float4 KsT4[32][33];       // [d4][kcol]    padded
    __shared__ float4 Vs4[32][33];        // [k][d4]       padded
    __shared__ float  Ps[32][AT_ROWS + 1];// [k][r]        padded

    const int tid  = threadIdx.x;
    const int lane = tid & 31;
    const int w    = tid >> 5;
    const int w4   = w * 4;
    const int b    = blockIdx.y >> 4;
    const int h    = blockIdx.y & 15;
    const int qt   = (int)(gridDim.x - 1 - blockIdx.x);   // heavy tiles first
    const int q0   = qt * AT_ROWS;

    const float scale = 0.08838834764831845f;   // 1/sqrt(128)
    const float* base = qkv + (size_t)(b * TT) * NQKV + h * HD;
    const float* kb_  = base + INNER;
    const float* vb_  = base + 2 * INNER;

    // Load Q tile (scaled): 16 rows x 32 d4 = 512 float4
#pragma unroll
    for (int i = 0; i < 4; ++i) {
        int idx = tid + i * 128;
        int r   = idx >> 5;
        int d4  = idx & 31;
        float4 v = *(const float4*)(base + (size_t)(q0 + r) * NQKV + d4 * 4);
        v.x *= scale; v.y *= scale; v.z *= scale; v.w *= scale;
        Qs4[d4][r] = v;
    }

    float mr[4], lr[4];
    float4 o[4];
#pragma unroll
    for (int r = 0; r < 4; ++r) {
        mr[r] = -1.0e30f; lr[r] = 0.0f;
        o[r] = make_float4(0.f, 0.f, 0.f, 0.f);
    }

    const int nkb = (q0 + AT_ROWS + 31) >> 5;

    for (int kb = 0; kb < nkb; ++kb) {
        __syncthreads();   // prior block's readers done before overwrite
        const int k0 = kb * 32;
        // Stage K (transposed) and V: 32 rows x 32 d4 each
#pragma unroll
        for (int i = 0; i < 8; ++i) {
            int idx = tid + i * 128;
            int kr  = idx >> 5;
            int d4  = idx & 31;
            KsT4[d4][kr] = *(const float4*)(kb_ + (size_t)(k0 + kr) * NQKV + d4 * 4);
            Vs4[kr][d4]  = *(const float4*)(vb_ + (size_t)(k0 + kr) * NQKV + d4 * 4);
        }
        __syncthreads();

        // S = Q K^T : lane owns k-column (k0+lane)
        float s[4] = {0.f, 0.f, 0.f, 0.f};
#pragma unroll 4
        for (int d4 = 0; d4 < 32; ++d4) {
            float4 kd = KsT4[d4][lane];
#pragma unroll
            for (int r = 0; r < 4; ++r) {
                float4 qv = Qs4[d4][w4 + r];
                s[r] = fmaf(qv.x, kd.x, s[r]);
                s[r] = fmaf(qv.y, kd.y, s[r]);
                s[r] = fmaf(qv.z, kd.z, s[r]);
                s[r] = fmaf(qv.w, kd.w, s[r]);
            }
        }
        const int kg = k0 + lane;
#pragma unroll
        for (int r = 0; r < 4; ++r)
            if (kg > q0 + w4 + r) s[r] = -1.0e30f;

        // Online softmax (per row; reductions once per 32-k block)
#pragma unroll
        for (int r = 0; r < 4; ++r) {
            float bm = s[r];
            bm = fmaxf(bm, __shfl_xor_sync(0xffffffffu, bm, 1));
            bm = fmaxf(bm, __shfl_xor_sync(0xffffffffu, bm, 2));
            bm = fmaxf(bm, __shfl_xor_sync(0xffffffffu, bm, 4));
            bm = fmaxf(bm, __shfl_xor_sync(0xffffffffu, bm, 8));
            bm = fmaxf(bm, __shfl_xor_sync(0xffffffffu, bm, 16));
            float mn    = fmaxf(mr[r], bm);
            float alpha = __expf(mr[r] - mn);
            float p     = __expf(s[r] - mn);
            mr[r] = mn;
            float ps = p;
            ps += __shfl_xor_sync(0xffffffffu, ps, 1);
            ps += __shfl_xor_sync(0xffffffffu, ps, 2);
            ps += __shfl_xor_sync(0xffffffffu, ps, 4);
            ps += __shfl_xor_sync(0xffffffffu, ps, 8);
            ps += __shfl_xor_sync(0xffffffffu, ps, 16);
            lr[r] = lr[r] * alpha + ps;
            o[r].x *= alpha; o[r].y *= alpha; o[r].z *= alpha; o[r].w *= alpha;
            Ps[lane][w4 + r] = p;
        }
        __syncwarp();   // warp reads its own rows' P written by all its lanes

        // O += P V : lane owns dims 4*lane..4*lane+3
#pragma unroll 4
        for (int k = 0; k < 32; ++k) {
            float4 vv = Vs4[k][lane];
#pragma unroll
            for (int r = 0; r < 4; ++r) {
                float p = Ps[k][w4 + r];
                o[r].x = fmaf(p, vv.x, o[r].x);
                o[r].y = fmaf(p, vv.y, o[r].y);
                o[r].z = fmaf(p, vv.z, o[r].z);
                o[r].w = fmaf(p, vv.w, o[r].w);
            }
        }
    }

#pragma unroll
    for (int r = 0; r < 4; ++r) {
        float inv = 1.0f / lr[r];
        float4 v = make_float4(o[r].x * inv, o[r].y * inv,
                               o[r].z * inv, o[r].w * inv);
        *(float4*)(outb + (size_t)(b * TT + q0 + w4 + r) * INNER
                   + h * HD + lane * 4) = v;
    }
}

// ---------------------------------------------------------------------------
// Entry point
// ---------------------------------------------------------------------------
extern "C" void kernel_launch(void* const* d_in, const int* in_sizes, int n_in,
                              void* d_out, int out_size)
{
    (void)out_size;
    const int NX = BB * TT * DIMM;   // 8388608
    const int NW = DIMM * NQKV;      // 12582912
    const int NO = INNER * DIMM;     // 4194304

    const float* x     = nullptr;
    const float* w_qkv = nullptr;
    const float* w_out = nullptr;
    for (int i = 0; i < n_in; ++i) {
        int sz = in_sizes[i];
        if      (sz == NX || sz == NX * 4) x     = (const float*)d_in[i];
        else if (sz == NW || sz == NW * 4) w_qkv = (const float*)d_in[i];
        else if (sz == NO || sz == NO * 4) w_out = (const float*)d_in[i];
    }
    if (!x || !w_qkv || !w_out) {
        x     = (const float*)d_in[0];
        w_qkv = (const float*)d_in[1];
        w_out = (const float*)d_in[2];
    }

    float* out = (float*)d_out;

    float *qkv_p, *attn_p;
    __nv_bfloat16 *ah, *al, *bh, *bl;
    cudaGetSymbolAddress((void**)&qkv_p,  g_qkv);
    cudaGetSymbolAddress((void**)&attn_p, g_attn);
    cudaGetSymbolAddress((void**)&ah, gA_hi);
    cudaGetSymbolAddress((void**)&al, gA_lo);
    cudaGetSymbolAddress((void**)&bh, gB_hi);
    cudaGetSymbolAddress((void**)&bl, gB_lo);

    cudaFuncSetAttribute(gemm_bf16x3,
                         cudaFuncAttributeMaxDynamicSharedMemorySize, GEMM_SMEM);

    // 1. RoPE tables
    table_kernel<<<(TT * 64) / 256, 256>>>();

    // 2. Split x -> bf16 hi/lo; transpose-split w_qkv
    conv_split<<<NX / 1024, 256>>>(x, ah, al);
    conv_split_T<<<dim3(NQKV / 32, DIMM / 32), dim3(32, 8)>>>(w_qkv, bh, bl,
                                                              DIMM, NQKV);
    // 3. QKV projection (mma.sync, 3-stage pipeline)
    gemm_bf16x3<<<dim3(NQKV / 128, MROWS / 128), 512, GEMM_SMEM>>>(
        ah, al, bh, bl, qkv_p, DIMM, NQKV);

    // 4. RoPE in place
    rope_kernel<<<(MROWS * HEADS * 64) / 256, 256>>>(qkv_p);

    // 5. Causal flash attention (CTA-tiled, smem K/V sharing)
    attn_kernel<<<dim3(TT / AT_ROWS, BB * HEADS), 128>>>(qkv_p, attn_p);

    // 6. Split attn output + transpose-split w_out; out projection
    conv_split<<<(MROWS * INNER) / 1024, 256>>>(attn_p, ah, al);
    conv_split_T<<<dim3(DIMM / 32, INNER / 32), dim3(32, 8)>>>(w_out, bh, bl,
                                                               INNER, DIMM);
    gemm_bf16x3<<<dim3(DIMM / 128, MROWS / 128), 512, GEMM_SMEM>>>(
        ah, al, bh, bl, out, INNER, DIMM);
}

// round 11
// speedup vs baseline: 3.0136x; 1.4964x over previous
#include <cuda_runtime.h>
#include <cuda_bf16.h>
#include <math.h>
#include <stdint.h>

#define TT    2048
#define BB    2
#define DIMM  2048
#define HEADS 16
#define HD    128
#define INNER 2048
#define NQKV  6144
#define MROWS 4096   // B*T

// ---------------------------------------------------------------------------
// Scratch (device globals; no allocations allowed)
// ---------------------------------------------------------------------------
__device__ float g_qkv[(size_t)MROWS * NQKV];   // [4096, 6144] q|k|v
__device__ float g_attn[(size_t)MROWS * INNER]; // [4096, 2048]
__device__ float g_cos[TT * 64];
__device__ float g_sin[TT * 64];
// bf16x3 operand buffers
__device__ __nv_bfloat16 gA_hi[(size_t)MROWS * DIMM];
__device__ __nv_bfloat16 gA_lo[(size_t)MROWS * DIMM];
__device__ __nv_bfloat16 gB_hi[(size_t)NQKV * DIMM];   // [N,K] transposed
__device__ __nv_bfloat16 gB_lo[(size_t)NQKV * DIMM];

// ---------------------------------------------------------------------------
// Portable PTX helpers (sm_80+): cp.async + mma.sync bf16
// ---------------------------------------------------------------------------
__device__ __forceinline__ uint32_t smem_u32(const void* p) {
    uint32_t a;
    asm("{ .reg .u64 t; cvta.to.shared.u64 t, %1; cvt.u32.u64 %0, t; }"
        : "=r"(a) : "l"(p));
    return a;
}
__device__ __forceinline__ void cp16(uint32_t saddr, const void* g) {
    asm volatile("cp.async.ca.shared.global [%0], [%1], 16;"
                 :: "r"(saddr), "l"(g) : "memory");
}
#define CP_COMMIT() asm volatile("cp.async.commit_group;" ::: "memory")
#define CP_WAIT0()  asm volatile("cp.async.wait_group 0;" ::: "memory")
#define CP_WAIT1()  asm volatile("cp.async.wait_group 1;" ::: "memory")

__device__ __forceinline__ void mma16816(float* c, const uint32_t* a,
                                         const uint32_t* b) {
    asm volatile(
        "mma.sync.aligned.m16n8k16.row.col.f32.bf16.bf16.f32 "
        "{%0,%1,%2,%3}, {%4,%5,%6,%7}, {%8,%9}, {%0,%1,%2,%3};"
        : "+f"(c[0]), "+f"(c[1]), "+f"(c[2]), "+f"(c[3])
        : "r"(a[0]), "r"(a[1]), "r"(a[2]), "r"(a[3]), "r"(b[0]), "r"(b[1]));
}

// ---------------------------------------------------------------------------
// RoPE cos/sin tables in fp64
// ---------------------------------------------------------------------------
__global__ void table_kernel() {
    int idx = blockIdx.x * 256 + threadIdx.x;
    int j = idx & 63;
    int t = idx >> 6;
    double inv = exp(-log(10000.0) * (double)j / 64.0);
    double ang = (double)t * inv;
    g_cos[idx] = (float)cos(ang);
    g_sin[idx] = (float)sin(ang);
}

// ---------------------------------------------------------------------------
// fp32 -> bf16 hi/lo split, same layout
// ---------------------------------------------------------------------------
__global__ __launch_bounds__(256) void conv_split(
    const float* __restrict__ src, __nv_bfloat16* __restrict__ hi,
    __nv_bfloat16* __restrict__ lo)
{
    int i = blockIdx.x * 256 + threadIdx.x;
    float4 v = ((const float4*)src)[i];
    float vv[4] = {v.x, v.y, v.z, v.w};
#pragma unroll
    for (int j = 0; j < 4; ++j) {
        __nv_bfloat16 h = __float2bfloat16(vv[j]);
        hi[i * 4 + j] = h;
        lo[i * 4 + j] = __float2bfloat16(vv[j] - __bfloat162float(h));
    }
}

// ---------------------------------------------------------------------------
// fp32 [K,N] -> transposed bf16 hi/lo [N,K]
// ---------------------------------------------------------------------------
__global__ __launch_bounds__(256) void conv_split_T(
    const float* __restrict__ src, __nv_bfloat16* __restrict__ hiT,
    __nv_bfloat16* __restrict__ loT, int K, int N)
{
    __shared__ float tile[32][33];
    int n0 = blockIdx.x * 32, k0 = blockIdx.y * 32;
    int tx = threadIdx.x, ty = threadIdx.y;
#pragma unroll
    for (int j = 0; j < 4; ++j)
        tile[ty + 8 * j][tx] = src[(size_t)(k0 + ty + 8 * j) * N + n0 + tx];
    __syncthreads();
#pragma unroll
    for (int j = 0; j < 4; ++j) {
        float v = tile[tx][ty + 8 * j];
        __nv_bfloat16 h = __float2bfloat16(v);
        size_t o = (size_t)(n0 + ty + 8 * j) * K + k0 + tx;
        hiT[o] = h;
        loT[o] = __float2bfloat16(v - __bfloat162float(h));
    }
}

// ---------------------------------------------------------------------------
// mma.sync bf16x3 GEMM, 3-stage cp.async pipeline, 2 CTAs/SM.
// CTA: 128x64 tile, 256 threads = 8 warps (4M x 2N), warp tile 32x32.
// ---------------------------------------------------------------------------
#define KC       32
#define ROWB     80
#define A_TILE_B (128 * ROWB)         // 10240
#define B_TILE_B (64 * ROWB)          // 5120
#define OFF_AH   0
#define OFF_AL   A_TILE_B             // 10240
#define OFF_BH   (2 * A_TILE_B)       // 20480
#define OFF_BL   (2 * A_TILE_B + B_TILE_B) // 25600
#define STAGE_B  (2 * A_TILE_B + 2 * B_TILE_B) // 30720
#define NSTAGE   3
#define GEMM_SMEM (NSTAGE * STAGE_B)  // 92160

__device__ __forceinline__ void load_chunk(
    uint32_t sbase,
    const __nv_bfloat16* __restrict__ Ah, const __nv_bfloat16* __restrict__ Al,
    const __nv_bfloat16* __restrict__ Bh, const __nv_bfloat16* __restrict__ Bl,
    int bm, int bn, int kc, int Kd, int tid)
{
    // A: 128 rows x 4 segs; each thread does 2 segs for hi and lo
    const int ra = tid >> 1;            // 0..127
    const int sa = (tid & 1) * 2;       // 0 or 2
    const size_t ga = (size_t)(bm + ra) * Kd + kc * KC + sa * 8;
    const uint32_t srA = sbase + ra * ROWB + sa * 16;
    cp16(srA + OFF_AH,      Ah + ga);
    cp16(srA + OFF_AH + 16, Ah + ga + 8);
    cp16(srA + OFF_AL,      Al + ga);
    cp16(srA + OFF_AL + 16, Al + ga + 8);
    // B: 64 rows x 4 segs; one seg per thread for hi and lo
    const int rb = tid >> 2;            // 0..63
    const int sb2 = tid & 3;
    const size_t gb = (size_t)(bn + rb) * Kd + kc * KC + sb2 * 8;
    const uint32_t srB = sbase + rb * ROWB + sb2 * 16;
    cp16(srB + OFF_BH, Bh + gb);
    cp16(srB + OFF_BL, Bl + gb);
}

__global__ __launch_bounds__(256, 2) void gemm_bf16x3(
    const __nv_bfloat16* __restrict__ Ah, const __nv_bfloat16* __restrict__ Al,
    const __nv_bfloat16* __restrict__ Bh, const __nv_bfloat16* __restrict__ Bl,
    float* __restrict__ C, int Kd, int Ncols)
{
    extern __shared__ char smem[];
    const uint32_t sb = smem_u32(smem);
    const int tid  = threadIdx.x;
    const int wid  = tid >> 5;
    const int lane = tid & 31;
    const int g    = lane >> 2;
    const int tig  = lane & 3;
    const int wm   = wid & 3;           // M offset 32*wm
    const int wn   = wid >> 2;          // 0..1 -> N offset 32*wn
    const int bm   = blockIdx.y * 128;
    const int bn   = blockIdx.x * 64;

    float acc[2][4][4];
#pragma unroll
    for (int ms = 0; ms < 2; ++ms)
#pragma unroll
        for (int ns = 0; ns < 4; ++ns)
#pragma unroll
            for (int q = 0; q < 4; ++q) acc[ms][ns][q] = 0.0f;

    const int NT = Kd / KC;

    load_chunk(sb, Ah, Al, Bh, Bl, bm, bn, 0, Kd, tid);
    CP_COMMIT();
    load_chunk(sb + STAGE_B, Ah, Al, Bh, Bl, bm, bn, 1, Kd, tid);
    CP_COMMIT();

    for (int kc = 0; kc < NT; ++kc) {
        if (kc + 1 < NT) { CP_WAIT1(); } else { CP_WAIT0(); }
        __syncthreads();
        if (kc + 2 < NT) {
            load_chunk(sb + ((kc + 2) % NSTAGE) * STAGE_B, Ah, Al, Bh, Bl,
                       bm, bn, kc + 2, Kd, tid);
            CP_COMMIT();
        }

        const char* st = smem + (kc % NSTAGE) * STAGE_B;
#pragma unroll
        for (int kk = 0; kk < 2; ++kk) {
            const int kbyte = kk * 32 + tig * 4;

            uint32_t afh[2][4], afl[2][4];
#pragma unroll
            for (int ms = 0; ms < 2; ++ms) {
                const char* ar = st + (wm * 32 + ms * 16 + g) * ROWB + kbyte;
                afh[ms][0] = *(const uint32_t*)(ar + OFF_AH);
                afh[ms][1] = *(const uint32_t*)(ar + OFF_AH + 8 * ROWB);
                afh[ms][2] = *(const uint32_t*)(ar + OFF_AH + 16);
                afh[ms][3] = *(const uint32_t*)(ar + OFF_AH + 8 * ROWB + 16);
                afl[ms][0] = *(const uint32_t*)(ar + OFF_AL);
                afl[ms][1] = *(const uint32_t*)(ar + OFF_AL + 8 * ROWB);
                afl[ms][2] = *(const uint32_t*)(ar + OFF_AL + 16);
                afl[ms][3] = *(const uint32_t*)(ar + OFF_AL + 8 * ROWB + 16);
            }
            uint32_t bfh[4][2], bfl[4][2];
#pragma unroll
            for (int ns = 0; ns < 4; ++ns) {
                const char* br = st + (wn * 32 + ns * 8 + g) * ROWB + kbyte;
                bfh[ns][0] = *(const uint32_t*)(br + OFF_BH);
                bfh[ns][1] = *(const uint32_t*)(br + OFF_BH + 16);
                bfl[ns][0] = *(const uint32_t*)(br + OFF_BL);
                bfl[ns][1] = *(const uint32_t*)(br + OFF_BL + 16);
            }
#pragma unroll
            for (int ms = 0; ms < 2; ++ms)
#pragma unroll
                for (int ns = 0; ns < 4; ++ns) {
                    mma16816(acc[ms][ns], afh[ms], bfh[ns]);
                    mma16816(acc[ms][ns], afh[ms], bfl[ns]);
                    mma16816(acc[ms][ns], afl[ms], bfh[ns]);
                }
        }
    }

    // Epilogue
#pragma unroll
    for (int ms = 0; ms < 2; ++ms) {
        const int row = bm + wm * 32 + ms * 16 + g;
#pragma unroll
        for (int ns = 0; ns < 4; ++ns) {
            const int col = bn + wn * 32 + ns * 8 + tig * 2;
            *(float2*)&C[(size_t)row * Ncols + col] =
                make_float2(acc[ms][ns][0], acc[ms][ns][1]);
            *(float2*)&C[(size_t)(row + 8) * Ncols + col] =
                make_float2(acc[ms][ns][2], acc[ms][ns][3]);
        }
    }
}

// ---------------------------------------------------------------------------
// RoPE in place on q and k sections (tables)
// ---------------------------------------------------------------------------
__global__ __launch_bounds__(256) void rope_kernel(float* __restrict__ qkv)
{
    int idx = blockIdx.x * 256 + threadIdx.x;   // < 4194304
    int j = idx & 63;
    int h = (idx >> 6) & 15;
    int m = idx >> 10;
    int t = m & (TT - 1);

    float c = g_cos[t * 64 + j];
    float s = g_sin[t * 64 + j];

    size_t base = (size_t)m * NQKV + h * HD + j;
    float q1 = qkv[base];
    float q2 = qkv[base + 64];
    qkv[base]      = q1 * c - q2 * s;
    qkv[base + 64] = q2 * c + q1 * s;

    size_t kb = base + INNER;
    float k1 = qkv[kb];
    float k2 = qkv[kb + 64];
    qkv[kb]      = k1 * c - k2 * s;
    qkv[kb + 64] = k2 * c + k1 * s;
}

// ---------------------------------------------------------------------------
// Causal flash attention, CTA-tiled (known-good from R9).
// CTA = 16 q rows (4 warps x 4 rows), K/V staged in smem in 32-k blocks.
// ---------------------------------------------------------------------------
#define AT_ROWS 16

__global__ __launch_bounds__(128) void attn_kernel(
    const float* __restrict__ qkv, float* __restrict__ outb)
{
    __shared__ float4 Qs4[32][AT_ROWS];   // [d4][r]
    __shared__ float4 KsT4[32][33];       // [d4][kcol] padded
    __shared__ float4 Vs4[32][33];        // [k][d4]    padded
    __shared__ float  Ps[32][AT_ROWS + 1];// [k][r]     padded

    const int tid  = threadIdx.x;
    const int lane = tid & 31;
    const int w    = tid >> 5;
    const int w4   = w * 4;
    const int b    = blockIdx.y >> 4;
    const int h    = blockIdx.y & 15;
    const int qt   = (int)(gridDim.x - 1 - blockIdx.x);
    const int q0   = qt * AT_ROWS;

    const float scale = 0.08838834764831845f;
    const float* base = qkv + (size_t)(b * TT) * NQKV + h * HD;
    const float* kb_  = base + INNER;
    const float* vb_  = base + 2 * INNER;

#pragma unroll
    for (int i = 0; i < 4; ++i) {
        int idx = tid + i * 128;
        int r   = idx >> 5;
        int d4  = idx & 31;
        float4 v = *(const float4*)(base + (size_t)(q0 + r) * NQKV + d4 * 4);
        v.x *= scale; v.y *= scale; v.z *= scale; v.w *= scale;
        Qs4[d4][r] = v;
    }

    float mr[4], lr[4];
    float4 o[4];
#pragma unroll
    for (int r = 0; r < 4; ++r) {
        mr[r] = -1.0e30f; lr[r] = 0.0f;
        o[r] = make_float4(0.f, 0.f, 0.f, 0.f);
    }

    const int nkb = (q0 + AT_ROWS + 31) >> 5;

    for (int kb = 0; kb < nkb; ++kb) {
        __syncthreads();
        const int k0 = kb * 32;
#pragma unroll
        for (int i = 0; i < 8; ++i) {
            int idx = tid + i * 128;
            int kr  = idx >> 5;
            int d4  = idx & 31;
            KsT4[d4][kr] = *(const float4*)(kb_ + (size_t)(k0 + kr) * NQKV + d4 * 4);
            Vs4[kr][d4]  = *(const float4*)(vb_ + (size_t)(k0 + kr) * NQKV + d4 * 4);
        }
        __syncthreads();

        float s[4] = {0.f, 0.f, 0.f, 0.f};
#pragma unroll 4
        for (int d4 = 0; d4 < 32; ++d4) {
            float4 kd = KsT4[d4][lane];
#pragma unroll
            for (int r = 0; r < 4; ++r) {
                float4 qv = Qs4[d4][w4 + r];
                s[r] = fmaf(qv.x, kd.x, s[r]);
                s[r] = fmaf(qv.y, kd.y, s[r]);
                s[r] = fmaf(qv.z, kd.z, s[r]);
                s[r] = fmaf(qv.w, kd.w, s[r]);
            }
        }
        const int kg = k0 + lane;
#pragma unroll
        for (int r = 0; r < 4; ++r)
            if (kg > q0 + w4 + r) s[r] = -1.0e30f;

#pragma unroll
        for (int r = 0; r < 4; ++r) {
            float bm = s[r];
            bm = fmaxf(bm, __shfl_xor_sync(0xffffffffu, bm, 1));
            bm = fmaxf(bm, __shfl_xor_sync(0xffffffffu, bm, 2));
            bm = fmaxf(bm, __shfl_xor_sync(0xffffffffu, bm, 4));
            bm = fmaxf(bm, __shfl_xor_sync(0xffffffffu, bm, 8));
            bm = fmaxf(bm, __shfl_xor_sync(0xffffffffu, bm, 16));
            float mn    = fmaxf(mr[r], bm);
            float alpha = __expf(mr[r] - mn);
            float p     = __expf(s[r] - mn);
            mr[r] = mn;
            float ps = p;
            ps += __shfl_xor_sync(0xffffffffu, ps, 1);
            ps += __shfl_xor_sync(0xffffffffu, ps, 2);
            ps += __shfl_xor_sync(0xffffffffu, ps, 4);
            ps += __shfl_xor_sync(0xffffffffu, ps, 8);
            ps += __shfl_xor_sync(0xffffffffu, ps, 16);
            lr[r] = lr[r] * alpha + ps;
            o[r].x *= alpha; o[r].y *= alpha; o[r].z *= alpha; o[r].w *= alpha;
            Ps[lane][w4 + r] = p;
        }
        __syncwarp();

#pragma unroll 4
        for (int k = 0; k < 32; ++k) {
            float4 vv = Vs4[k][lane];
#pragma unroll
            for (int r = 0; r < 4; ++r) {
                float p = Ps[k][w4 + r];
                o[r].x = fmaf(p, vv.x, o[r].x);
                o[r].y = fmaf(p, vv.y, o[r].y);
                o[r].z = fmaf(p, vv.z, o[r].z);
                o[r].w = fmaf(p, vv.w, o[r].w);
            }
        }
    }

#pragma unroll
    for (int r = 0; r < 4; ++r) {
        float inv = 1.0f / lr[r];
        float4 v = make_float4(o[r].x * inv, o[r].y * inv,
                               o[r].z * inv, o[r].w * inv);
        *(float4*)(outb + (size_t)(b * TT + q0 + w4 + r) * INNER
                   + h * HD + lane * 4) = v;
    }
}

// ---------------------------------------------------------------------------
// Entry point
// ---------------------------------------------------------------------------
extern "C" void kernel_launch(void* const* d_in, const int* in_sizes, int n_in,
                              void* d_out, int out_size)
{
    (void)out_size;
    const int NX = BB * TT * DIMM;   // 8388608
    const int NW = DIMM * NQKV;      // 12582912
    const int NO = INNER * DIMM;     // 4194304

    const float* x     = nullptr;
    const float* w_qkv = nullptr;
    const float* w_out = nullptr;
    for (int i = 0; i < n_in; ++i) {
        int sz = in_sizes[i];
        if      (sz == NX || sz == NX * 4) x     = (const float*)d_in[i];
        else if (sz == NW || sz == NW * 4) w_qkv = (const float*)d_in[i];
        else if (sz == NO || sz == NO * 4) w_out = (const float*)d_in[i];
    }
    if (!x || !w_qkv || !w_out) {
        x     = (const float*)d_in[0];
        w_qkv = (const float*)d_in[1];
        w_out = (const float*)d_in[2];
    }

    float* out = (float*)d_out;

    float *qkv_p, *attn_p;
    __nv_bfloat16 *ah, *al, *bh, *bl;
    cudaGetSymbolAddress((void**)&qkv_p,  g_qkv);
    cudaGetSymbolAddress((void**)&attn_p, g_attn);
    cudaGetSymbolAddress((void**)&ah, gA_hi);
    cudaGetSymbolAddress((void**)&al, gA_lo);
    cudaGetSymbolAddress((void**)&bh, gB_hi);
    cudaGetSymbolAddress((void**)&bl, gB_lo);

    cudaFuncSetAttribute(gemm_bf16x3,
                         cudaFuncAttributeMaxDynamicSharedMemorySize, GEMM_SMEM);

    // 1. RoPE tables
    table_kernel<<<(TT * 64) / 256, 256>>>();

    // 2. Split x -> bf16 hi/lo; transpose-split w_qkv
    conv_split<<<NX / 1024, 256>>>(x, ah, al);
    conv_split_T<<<dim3(NQKV / 32, DIMM / 32), dim3(32, 8)>>>(w_qkv, bh, bl,
                                                              DIMM, NQKV);
    // 3. QKV projection (mma.sync, 128x64 tiles, 2 CTAs/SM)
    gemm_bf16x3<<<dim3(NQKV / 64, MROWS / 128), 256, GEMM_SMEM>>>(
        ah, al, bh, bl, qkv_p, DIMM, NQKV);

    // 4. RoPE in place
    rope_kernel<<<(MROWS * HEADS * 64) / 256, 256>>>(qkv_p);

    // 5. Causal flash attention
    attn_kernel<<<dim3(TT / AT_ROWS, BB * HEADS), 128>>>(qkv_p, attn_p);

    // 6. Split attn output + transpose-split w_out; out projection
    conv_split<<<(MROWS * INNER) / 1024, 256>>>(attn_p, ah, al);
    conv_split_T<<<dim3(DIMM / 32, INNER / 32), dim3(32, 8)>>>(w_out, bh, bl,
                                                               INNER, DIMM);
    gemm_bf16x3<<<dim3(DIMM / 64, MROWS / 128), 256, GEMM_SMEM>>>(
        ah, al, bh, bl, out, INNER, DIMM);
}

// round 12
// speedup vs baseline: 3.2929x; 1.0927x over previous
#include <cuda_runtime.h>
#include <cuda_bf16.h>
#include <math.h>
#include <stdint.h>

#define TT    2048
#define BB    2
#define DIMM  2048
#define HEADS 16
#define HD    128
#define INNER 2048
#define NQKV  6144
#define MROWS 4096   // B*T

// ---------------------------------------------------------------------------
// Scratch (device globals; no allocations allowed)
// ---------------------------------------------------------------------------
__device__ float g_qkv[(size_t)MROWS * NQKV];   // [4096, 6144] q|k|v
__device__ float g_attn[(size_t)MROWS * INNER]; // [4096, 2048]
__device__ float g_cos[TT * 64];
__device__ float g_sin[TT * 64];
// bf16x3 operand buffers
__device__ __nv_bfloat16 gA_hi[(size_t)MROWS * DIMM];
__device__ __nv_bfloat16 gA_lo[(size_t)MROWS * DIMM];
__device__ __nv_bfloat16 gB_hi[(size_t)NQKV * DIMM];   // [N,K] transposed
__device__ __nv_bfloat16 gB_lo[(size_t)NQKV * DIMM];

// ---------------------------------------------------------------------------
// Portable PTX helpers (sm_80+): cp.async + mma.sync bf16
// ---------------------------------------------------------------------------
__device__ __forceinline__ uint32_t smem_u32(const void* p) {
    uint32_t a;
    asm("{ .reg .u64 t; cvta.to.shared.u64 t, %1; cvt.u32.u64 %0, t; }"
        : "=r"(a) : "l"(p));
    return a;
}
__device__ __forceinline__ void cp16(uint32_t saddr, const void* g) {
    asm volatile("cp.async.ca.shared.global [%0], [%1], 16;"
                 :: "r"(saddr), "l"(g) : "memory");
}
#define CP_COMMIT() asm volatile("cp.async.commit_group;" ::: "memory")
#define CP_WAIT0()  asm volatile("cp.async.wait_group 0;" ::: "memory")
#define CP_WAIT1()  asm volatile("cp.async.wait_group 1;" ::: "memory")

__device__ __forceinline__ void mma16816(float* c, const uint32_t* a,
                                         const uint32_t* b) {
    asm volatile(
        "mma.sync.aligned.m16n8k16.row.col.f32.bf16.bf16.f32 "
        "{%0,%1,%2,%3}, {%4,%5,%6,%7}, {%8,%9}, {%0,%1,%2,%3};"
        : "+f"(c[0]), "+f"(c[1]), "+f"(c[2]), "+f"(c[3])
        : "r"(a[0]), "r"(a[1]), "r"(a[2]), "r"(a[3]), "r"(b[0]), "r"(b[1]));
}

// ---------------------------------------------------------------------------
// RoPE cos/sin tables in fp64
// ---------------------------------------------------------------------------
__global__ void table_kernel() {
    int idx = blockIdx.x * 256 + threadIdx.x;
    int j = idx & 63;
    int t = idx >> 6;
    double inv = exp(-log(10000.0) * (double)j / 64.0);
    double ang = (double)t * inv;
    g_cos[idx] = (float)cos(ang);
    g_sin[idx] = (float)sin(ang);
}

// ---------------------------------------------------------------------------
// fp32 -> bf16 hi/lo split, same layout
// ---------------------------------------------------------------------------
__global__ __launch_bounds__(256) void conv_split(
    const float* __restrict__ src, __nv_bfloat16* __restrict__ hi,
    __nv_bfloat16* __restrict__ lo)
{
    int i = blockIdx.x * 256 + threadIdx.x;
    float4 v = ((const float4*)src)[i];
    float vv[4] = {v.x, v.y, v.z, v.w};
#pragma unroll
    for (int j = 0; j < 4; ++j) {
        __nv_bfloat16 h = __float2bfloat16(vv[j]);
        hi[i * 4 + j] = h;
        lo[i * 4 + j] = __float2bfloat16(vv[j] - __bfloat162float(h));
    }
}

// ---------------------------------------------------------------------------
// fp32 [K,N] -> transposed bf16 hi/lo [N,K]
// ---------------------------------------------------------------------------
__global__ __launch_bounds__(256) void conv_split_T(
    const float* __restrict__ src, __nv_bfloat16* __restrict__ hiT,
    __nv_bfloat16* __restrict__ loT, int K, int N)
{
    __shared__ float tile[32][33];
    int n0 = blockIdx.x * 32, k0 = blockIdx.y * 32;
    int tx = threadIdx.x, ty = threadIdx.y;
#pragma unroll
    for (int j = 0; j < 4; ++j)
        tile[ty + 8 * j][tx] = src[(size_t)(k0 + ty + 8 * j) * N + n0 + tx];
    __syncthreads();
#pragma unroll
    for (int j = 0; j < 4; ++j) {
        float v = tile[tx][ty + 8 * j];
        __nv_bfloat16 h = __float2bfloat16(v);
        size_t o = (size_t)(n0 + ty + 8 * j) * K + k0 + tx;
        hiT[o] = h;
        loT[o] = __float2bfloat16(v - __bfloat162float(h));
    }
}

// ---------------------------------------------------------------------------
// mma.sync bf16x3 GEMM, 2-stage cp.async pipeline, 2 CTAs/SM.
// CTA: 128x128 tile, 256 threads = 8 warps (4M x 2N), warp tile 32x64.
// Per-FLOP smem fragment traffic halved vs 32x32 warp tiles.
// ---------------------------------------------------------------------------
#define KC       32
#define ROWB     80
#define A_TILE_B (128 * ROWB)              // 10240
#define B_TILE_B (128 * ROWB)              // 10240
#define OFF_AH   0
#define OFF_AL   A_TILE_B                  // 10240
#define OFF_BH   (2 * A_TILE_B)            // 20480
#define OFF_BL   (3 * A_TILE_B)            // 30720
#define STAGE_B  (4 * A_TILE_B)            // 40960
#define NSTAGE   2
#define GEMM_SMEM (NSTAGE * STAGE_B)       // 81920

__device__ __forceinline__ void load_chunk(
    uint32_t sbase,
    const __nv_bfloat16* __restrict__ Ah, const __nv_bfloat16* __restrict__ Al,
    const __nv_bfloat16* __restrict__ Bh, const __nv_bfloat16* __restrict__ Bl,
    int bm, int bn, int kc, int Kd, int tid)
{
    const int r = tid >> 1;             // 0..127
    const int s = (tid & 1) * 2;        // 0 or 2 (16B segs within 64B row)
    const size_t ga = (size_t)(bm + r) * Kd + kc * KC + s * 8;
    const size_t gb = (size_t)(bn + r) * Kd + kc * KC + s * 8;
    const uint32_t srow = sbase + r * ROWB + s * 16;
    cp16(srow + OFF_AH,      Ah + ga);
    cp16(srow + OFF_AH + 16, Ah + ga + 8);
    cp16(srow + OFF_AL,      Al + ga);
    cp16(srow + OFF_AL + 16, Al + ga + 8);
    cp16(srow + OFF_BH,      Bh + gb);
    cp16(srow + OFF_BH + 16, Bh + gb + 8);
    cp16(srow + OFF_BL,      Bl + gb);
    cp16(srow + OFF_BL + 16, Bl + gb + 8);
}

__global__ __launch_bounds__(256, 2) void gemm_bf16x3(
    const __nv_bfloat16* __restrict__ Ah, const __nv_bfloat16* __restrict__ Al,
    const __nv_bfloat16* __restrict__ Bh, const __nv_bfloat16* __restrict__ Bl,
    float* __restrict__ C, int Kd, int Ncols)
{
    extern __shared__ char smem[];
    const uint32_t sb = smem_u32(smem);
    const int tid  = threadIdx.x;
    const int wid  = tid >> 5;
    const int lane = tid & 31;
    const int g    = lane >> 2;
    const int tig  = lane & 3;
    const int wm   = wid & 3;           // M offset 32*wm
    const int wn   = wid >> 2;          // 0..1 -> N offset 64*wn
    const int bm   = blockIdx.y * 128;
    const int bn   = blockIdx.x * 128;

    float acc[2][8][4];
#pragma unroll
    for (int ms = 0; ms < 2; ++ms)
#pragma unroll
        for (int ns = 0; ns < 8; ++ns)
#pragma unroll
            for (int q = 0; q < 4; ++q) acc[ms][ns][q] = 0.0f;

    const int NT = Kd / KC;

    load_chunk(sb, Ah, Al, Bh, Bl, bm, bn, 0, Kd, tid);
    CP_COMMIT();

    for (int kc = 0; kc < NT; ++kc) {
        const int cur = kc & 1;
        if (kc + 1 < NT) {
            load_chunk(sb + (cur ^ 1) * STAGE_B, Ah, Al, Bh, Bl,
                       bm, bn, kc + 1, Kd, tid);
            CP_COMMIT();
            CP_WAIT1();
        } else {
            CP_WAIT0();
        }
        __syncthreads();

        const char* st = smem + cur * STAGE_B;
#pragma unroll
        for (int kk = 0; kk < 2; ++kk) {
            const int kbyte = kk * 32 + tig * 4;

            uint32_t afh[2][4], afl[2][4];
#pragma unroll
            for (int ms = 0; ms < 2; ++ms) {
                const char* ar = st + (wm * 32 + ms * 16 + g) * ROWB + kbyte;
                afh[ms][0] = *(const uint32_t*)(ar + OFF_AH);
                afh[ms][1] = *(const uint32_t*)(ar + OFF_AH + 8 * ROWB);
                afh[ms][2] = *(const uint32_t*)(ar + OFF_AH + 16);
                afh[ms][3] = *(const uint32_t*)(ar + OFF_AH + 8 * ROWB + 16);
                afl[ms][0] = *(const uint32_t*)(ar + OFF_AL);
                afl[ms][1] = *(const uint32_t*)(ar + OFF_AL + 8 * ROWB);
                afl[ms][2] = *(const uint32_t*)(ar + OFF_AL + 16);
                afl[ms][3] = *(const uint32_t*)(ar + OFF_AL + 8 * ROWB + 16);
            }
#pragma unroll
            for (int ns = 0; ns < 8; ++ns) {
                const char* br = st + (wn * 64 + ns * 8 + g) * ROWB + kbyte;
                uint32_t bfh[2], bfl[2];
                bfh[0] = *(const uint32_t*)(br + OFF_BH);
                bfh[1] = *(const uint32_t*)(br + OFF_BH + 16);
                bfl[0] = *(const uint32_t*)(br + OFF_BL);
                bfl[1] = *(const uint32_t*)(br + OFF_BL + 16);
#pragma unroll
                for (int ms = 0; ms < 2; ++ms) {
                    mma16816(acc[ms][ns], afh[ms], bfh);
                    mma16816(acc[ms][ns], afh[ms], bfl);
                    mma16816(acc[ms][ns], afl[ms], bfh);
                }
            }
        }
        __syncthreads();
    }

    // Epilogue
#pragma unroll
    for (int ms = 0; ms < 2; ++ms) {
        const int row = bm + wm * 32 + ms * 16 + g;
#pragma unroll
        for (int ns = 0; ns < 8; ++ns) {
            const int col = bn + wn * 64 + ns * 8 + tig * 2;
            *(float2*)&C[(size_t)row * Ncols + col] =
                make_float2(acc[ms][ns][0], acc[ms][ns][1]);
            *(float2*)&C[(size_t)(row + 8) * Ncols + col] =
                make_float2(acc[ms][ns][2], acc[ms][ns][3]);
        }
    }
}

// ---------------------------------------------------------------------------
// RoPE in place on q and k sections (tables)
// ---------------------------------------------------------------------------
__global__ __launch_bounds__(256) void rope_kernel(float* __restrict__ qkv)
{
    int idx = blockIdx.x * 256 + threadIdx.x;   // < 4194304
    int j = idx & 63;
    int h = (idx >> 6) & 15;
    int m = idx >> 10;
    int t = m & (TT - 1);

    float c = g_cos[t * 64 + j];
    float s = g_sin[t * 64 + j];

    size_t base = (size_t)m * NQKV + h * HD + j;
    float q1 = qkv[base];
    float q2 = qkv[base + 64];
    qkv[base]      = q1 * c - q2 * s;
    qkv[base + 64] = q2 * c + q1 * s;

    size_t kb = base + INNER;
    float k1 = qkv[kb];
    float k2 = qkv[kb + 64];
    qkv[kb]      = k1 * c - k2 * s;
    qkv[kb + 64] = k2 * c + k1 * s;
}

// ---------------------------------------------------------------------------
// Causal flash attention, CTA-tiled (known-good).
// CTA = 16 q rows (4 warps x 4 rows), K/V staged in smem in 32-k blocks.
// ---------------------------------------------------------------------------
#define AT_ROWS 16

__global__ __launch_bounds__(128) void attn_kernel(
    const float* __restrict__ qkv, float* __restrict__ outb)
{
    __shared__ float4 Qs4[32][AT_ROWS];   // [d4][r]
    __shared__ float4 KsT4[32][33];       // [d4][kcol] padded
    __shared__ float4 Vs4[32][33];        // [k][d4]    padded
    __shared__ float  Ps[32][AT_ROWS + 1];// [k][r]     padded

    const int tid  = threadIdx.x;
    const int lane = tid & 31;
    const int w    = tid >> 5;
    const int w4   = w * 4;
    const int b    = blockIdx.y >> 4;
    const int h    = blockIdx.y & 15;
    const int qt   = (int)(gridDim.x - 1 - blockIdx.x);
    const int q0   = qt * AT_ROWS;

    const float scale = 0.08838834764831845f;
    const float* base = qkv + (size_t)(b * TT) * NQKV + h * HD;
    const float* kb_  = base + INNER;
    const float* vb_  = base + 2 * INNER;

#pragma unroll
    for (int i = 0; i < 4; ++i) {
        int idx = tid + i * 128;
        int r   = idx >> 5;
        int d4  = idx & 31;
        float4 v = *(const float4*)(base + (size_t)(q0 + r) * NQKV + d4 * 4);
        v.x *= scale; v.y *= scale; v.z *= scale; v.w *= scale;
        Qs4[d4][r] = v;
    }

    float mr[4], lr[4];
    float4 o[4];
#pragma unroll
    for (int r = 0; r < 4; ++r) {
        mr[r] = -1.0e30f; lr[r] = 0.0f;
        o[r] = make_float4(0.f, 0.f, 0.f, 0.f);
    }

    const int nkb = (q0 + AT_ROWS + 31) >> 5;

    for (int kb = 0; kb < nkb; ++kb) {
        __syncthreads();
        const int k0 = kb * 32;
#pragma unroll
        for (int i = 0; i < 8; ++i) {
            int idx = tid + i * 128;
            int kr  = idx >> 5;
            int d4  = idx & 31;
            KsT4[d4][kr] = *(const float4*)(kb_ + (size_t)(k0 + kr) * NQKV + d4 * 4);
            Vs4[kr][d4]  = *(const float4*)(vb_ + (size_t)(k0 + kr) * NQKV + d4 * 4);
        }
        __syncthreads();

        float s[4] = {0.f, 0.f, 0.f, 0.f};
#pragma unroll 4
        for (int d4 = 0; d4 < 32; ++d4) {
            float4 kd = KsT4[d4][lane];
#pragma unroll
            for (int r = 0; r < 4; ++r) {
                float4 qv = Qs4[d4][w4 + r];
                s[r] = fmaf(qv.x, kd.x, s[r]);
                s[r] = fmaf(qv.y, kd.y, s[r]);
                s[r] = fmaf(qv.z, kd.z, s[r]);
                s[r] = fmaf(qv.w, kd.w, s[r]);
            }
        }
        const int kg = k0 + lane;
#pragma unroll
        for (int r = 0; r < 4; ++r)
            if (kg > q0 + w4 + r) s[r] = -1.0e30f;

#pragma unroll
        for (int r = 0; r < 4; ++r) {
            float bm = s[r];
            bm = fmaxf(bm, __shfl_xor_sync(0xffffffffu, bm, 1));
            bm = fmaxf(bm, __shfl_xor_sync(0xffffffffu, bm, 2));
            bm = fmaxf(bm, __shfl_xor_sync(0xffffffffu, bm, 4));
            bm = fmaxf(bm, __shfl_xor_sync(0xffffffffu, bm, 8));
            bm = fmaxf(bm, __shfl_xor_sync(0xffffffffu, bm, 16));
            float mn    = fmaxf(mr[r], bm);
            float alpha = __expf(mr[r] - mn);
            float p     = __expf(s[r] - mn);
            mr[r] = mn;
            float ps = p;
            ps += __shfl_xor_sync(0xffffffffu, ps, 1);
            ps += __shfl_xor_sync(0xffffffffu, ps, 2);
            ps += __shfl_xor_sync(0xffffffffu, ps, 4);
            ps += __shfl_xor_sync(0xffffffffu, ps, 8);
            ps += __shfl_xor_sync(0xffffffffu, ps, 16);
            lr[r] = lr[r] * alpha + ps;
            o[r].x *= alpha; o[r].y *= alpha; o[r].z *= alpha; o[r].w *= alpha;
            Ps[lane][w4 + r] = p;
        }
        __syncwarp();

#pragma unroll 4
        for (int k = 0; k < 32; ++k) {
            float4 vv = Vs4[k][lane];
#pragma unroll
            for (int r = 0; r < 4; ++r) {
                float p = Ps[k][w4 + r];
                o[r].x = fmaf(p, vv.x, o[r].x);
                o[r].y = fmaf(p, vv.y, o[r].y);
                o[r].z = fmaf(p, vv.z, o[r].z);
                o[r].w = fmaf(p, vv.w, o[r].w);
            }
        }
    }

#pragma unroll
    for (int r = 0; r < 4; ++r) {
        float inv = 1.0f / lr[r];
        float4 v = make_float4(o[r].x * inv, o[r].y * inv,
                               o[r].z * inv, o[r].w * inv);
        *(float4*)(outb + (size_t)(b * TT + q0 + w4 + r) * INNER
                   + h * HD + lane * 4) = v;
    }
}

// ---------------------------------------------------------------------------
// Entry point
// ---------------------------------------------------------------------------
extern "C" void kernel_launch(void* const* d_in, const int* in_sizes, int n_in,
                              void* d_out, int out_size)
{
    (void)out_size;
    const int NX = BB * TT * DIMM;   // 8388608
    const int NW = DIMM * NQKV;      // 12582912
    const int NO = INNER * DIMM;     // 4194304

    const float* x     = nullptr;
    const float* w_qkv = nullptr;
    const float* w_out = nullptr;
    for (int i = 0; i < n_in; ++i) {
        int sz = in_sizes[i];
        if      (sz == NX || sz == NX * 4) x     = (const float*)d_in[i];
        else if (sz == NW || sz == NW * 4) w_qkv = (const float*)d_in[i];
        else if (sz == NO || sz == NO * 4) w_out = (const float*)d_in[i];
    }
    if (!x || !w_qkv || !w_out) {
        x     = (const float*)d_in[0];
        w_qkv = (const float*)d_in[1];
        w_out = (const float*)d_in[2];
    }

    float* out = (float*)d_out;

    float *qkv_p, *attn_p;
    __nv_bfloat16 *ah, *al, *bh, *bl;
    cudaGetSymbolAddress((void**)&qkv_p,  g_qkv);
    cudaGetSymbolAddress((void**)&attn_p, g_attn);
    cudaGetSymbolAddress((void**)&ah, gA_hi);
    cudaGetSymbolAddress((void**)&al, gA_lo);
    cudaGetSymbolAddress((void**)&bh, gB_hi);
    cudaGetSymbolAddress((void**)&bl, gB_lo);

    cudaFuncSetAttribute(gemm_bf16x3,
                         cudaFuncAttributeMaxDynamicSharedMemorySize, GEMM_SMEM);

    // 1. RoPE tables
    table_kernel<<<(TT * 64) / 256, 256>>>();

    // 2. Split x -> bf16 hi/lo; transpose-split w_qkv
    conv_split<<<NX / 1024, 256>>>(x, ah, al);
    conv_split_T<<<dim3(NQKV / 32, DIMM / 32), dim3(32, 8)>>>(w_qkv, bh, bl,
                                                              DIMM, NQKV);
    // 3. QKV projection (mma.sync, 128x128 tiles, warp 32x64, 2 CTAs/SM)
    gemm_bf16x3<<<dim3(NQKV / 128, MROWS / 128), 256, GEMM_SMEM>>>(
        ah, al, bh, bl, qkv_p, DIMM, NQKV);

    // 4. RoPE in place
    rope_kernel<<<(MROWS * HEADS * 64) / 256, 256>>>(qkv_p);

    // 5. Causal flash attention
    attn_kernel<<<dim3(TT / AT_ROWS, BB * HEADS), 128>>>(qkv_p, attn_p);

    // 6. Split attn output + transpose-split w_out; out projection
    conv_split<<<(MROWS * INNER) / 1024, 256>>>(attn_p, ah, al);
    conv_split_T<<<dim3(DIMM / 32, INNER / 32), dim3(32, 8)>>>(w_out, bh, bl,
                                                               INNER, DIMM);
    gemm_bf16x3<<<dim3(DIMM / 128, MROWS / 128), 256, GEMM_SMEM>>>(
        ah, al, bh, bl, out, INNER, DIMM);
}

// round 13
// speedup vs baseline: 3.8667x; 1.1742x over previous
#include <cuda_runtime.h>
#include <cuda_fp16.h>
#include <math.h>
#include <stdint.h>

#define TT    2048
#define BB    2
#define DIMM  2048
#define HEADS 16
#define HD    128
#define INNER 2048
#define NQKV  6144
#define MROWS 4096   // B*T

// ---------------------------------------------------------------------------
// Scratch (device globals; no allocations allowed)
// ---------------------------------------------------------------------------
__device__ float g_qkv[(size_t)MROWS * NQKV];   // [4096, 6144] q|k|v
__device__ float g_attn[(size_t)MROWS * INNER]; // [4096, 2048]
__device__ float g_cos[TT * 64];
__device__ float g_sin[TT * 64];
// fp16 operand buffers
__device__ __half gA_hi[(size_t)MROWS * DIMM];
__device__ __half gA_lo[(size_t)MROWS * DIMM];
__device__ __half gB_hi[(size_t)NQKV * DIMM];   // [N,K] transposed, single fp16

// ---------------------------------------------------------------------------
// Portable PTX helpers (sm_80+): cp.async + mma.sync fp16
// ---------------------------------------------------------------------------
__device__ __forceinline__ uint32_t smem_u32(const void* p) {
    uint32_t a;
    asm("{ .reg .u64 t; cvta.to.shared.u64 t, %1; cvt.u32.u64 %0, t; }"
        : "=r"(a) : "l"(p));
    return a;
}
__device__ __forceinline__ void cp16(uint32_t saddr, const void* g) {
    asm volatile("cp.async.ca.shared.global [%0], [%1], 16;"
                 :: "r"(saddr), "l"(g) : "memory");
}
#define CP_COMMIT() asm volatile("cp.async.commit_group;" ::: "memory")
#define CP_WAIT0()  asm volatile("cp.async.wait_group 0;" ::: "memory")
#define CP_WAIT1()  asm volatile("cp.async.wait_group 1;" ::: "memory")

__device__ __forceinline__ void mma16816(float* c, const uint32_t* a,
                                         const uint32_t* b) {
    asm volatile(
        "mma.sync.aligned.m16n8k16.row.col.f32.f16.f16.f32 "
        "{%0,%1,%2,%3}, {%4,%5,%6,%7}, {%8,%9}, {%0,%1,%2,%3};"
        : "+f"(c[0]), "+f"(c[1]), "+f"(c[2]), "+f"(c[3])
        : "r"(a[0]), "r"(a[1]), "r"(a[2]), "r"(a[3]), "r"(b[0]), "r"(b[1]));
}

// ---------------------------------------------------------------------------
// RoPE cos/sin tables in fp64
// ---------------------------------------------------------------------------
__global__ void table_kernel() {
    int idx = blockIdx.x * 256 + threadIdx.x;
    int j = idx & 63;
    int t = idx >> 6;
    double inv = exp(-log(10000.0) * (double)j / 64.0);
    double ang = (double)t * inv;
    g_cos[idx] = (float)cos(ang);
    g_sin[idx] = (float)sin(ang);
}

// ---------------------------------------------------------------------------
// fp32 -> fp16 hi/lo split, same layout (A operand)
// ---------------------------------------------------------------------------
__global__ __launch_bounds__(256) void conv_split(
    const float* __restrict__ src, __half* __restrict__ hi,
    __half* __restrict__ lo)
{
    int i = blockIdx.x * 256 + threadIdx.x;
    float4 v = ((const float4*)src)[i];
    float vv[4] = {v.x, v.y, v.z, v.w};
#pragma unroll
    for (int j = 0; j < 4; ++j) {
        __half h = __float2half(vv[j]);
        hi[i * 4 + j] = h;
        lo[i * 4 + j] = __float2half(vv[j] - __half2float(h));
    }
}

// ---------------------------------------------------------------------------
// fp32 [K,N] -> transposed single fp16 [N,K] (B operand)
// ---------------------------------------------------------------------------
__global__ __launch_bounds__(256) void conv_T(
    const float* __restrict__ src, __half* __restrict__ hiT, int K, int N)
{
    __shared__ float tile[32][33];
    int n0 = blockIdx.x * 32, k0 = blockIdx.y * 32;
    int tx = threadIdx.x, ty = threadIdx.y;
#pragma unroll
    for (int j = 0; j < 4; ++j)
        tile[ty + 8 * j][tx] = src[(size_t)(k0 + ty + 8 * j) * N + n0 + tx];
    __syncthreads();
#pragma unroll
    for (int j = 0; j < 4; ++j) {
        float v = tile[tx][ty + 8 * j];
        hiT[(size_t)(n0 + ty + 8 * j) * K + k0 + tx] = __float2half(v);
    }
}

// ---------------------------------------------------------------------------
// mma.sync fp16x2 GEMM.  C = (Ah+Al) @ Bh^T, 2 MMAs per sub-tile.
// CTA: 128x128 tile, 256 threads = 8 warps (4M x 2N), warp tile 32x64.
// 2-stage cp.async pipeline, 2 CTAs/SM.
// ---------------------------------------------------------------------------
#define KC       32
#define ROWB     80
#define A_TILE_B (128 * ROWB)              // 10240
#define OFF_AH   0
#define OFF_AL   A_TILE_B                  // 10240
#define OFF_BH   (2 * A_TILE_B)            // 20480
#define STAGE_B  (3 * A_TILE_B)            // 30720
#define NSTAGE   2
#define GEMM_SMEM (NSTAGE * STAGE_B)       // 61440

__device__ __forceinline__ void load_chunk(
    uint32_t sbase,
    const __half* __restrict__ Ah, const __half* __restrict__ Al,
    const __half* __restrict__ Bh,
    int bm, int bn, int kc, int Kd, int tid)
{
    const int r = tid >> 1;             // 0..127
    const int s = (tid & 1) * 2;        // 0 or 2 (16B segs within 64B row)
    const size_t ga = (size_t)(bm + r) * Kd + kc * KC + s * 8;
    const size_t gb = (size_t)(bn + r) * Kd + kc * KC + s * 8;
    const uint32_t srow = sbase + r * ROWB + s * 16;
    cp16(srow + OFF_AH,      Ah + ga);
    cp16(srow + OFF_AH + 16, Ah + ga + 8);
    cp16(srow + OFF_AL,      Al + ga);
    cp16(srow + OFF_AL + 16, Al + ga + 8);
    cp16(srow + OFF_BH,      Bh + gb);
    cp16(srow + OFF_BH + 16, Bh + gb + 8);
}

__global__ __launch_bounds__(256, 2) void gemm_fp16x2(
    const __half* __restrict__ Ah, const __half* __restrict__ Al,
    const __half* __restrict__ Bh,
    float* __restrict__ C, int Kd, int Ncols)
{
    extern __shared__ char smem[];
    const uint32_t sb = smem_u32(smem);
    const int tid  = threadIdx.x;
    const int wid  = tid >> 5;
    const int lane = tid & 31;
    const int g    = lane >> 2;
    const int tig  = lane & 3;
    const int wm   = wid & 3;           // M offset 32*wm
    const int wn   = wid >> 2;          // 0..1 -> N offset 64*wn
    const int bm   = blockIdx.y * 128;
    const int bn   = blockIdx.x * 128;

    float acc[2][8][4];
#pragma unroll
    for (int ms = 0; ms < 2; ++ms)
#pragma unroll
        for (int ns = 0; ns < 8; ++ns)
#pragma unroll
            for (int q = 0; q < 4; ++q) acc[ms][ns][q] = 0.0f;

    const int NT = Kd / KC;

    load_chunk(sb, Ah, Al, Bh, bm, bn, 0, Kd, tid);
    CP_COMMIT();

    for (int kc = 0; kc < NT; ++kc) {
        const int cur = kc & 1;
        if (kc + 1 < NT) {
            load_chunk(sb + (cur ^ 1) * STAGE_B, Ah, Al, Bh,
                       bm, bn, kc + 1, Kd, tid);
            CP_COMMIT();
            CP_WAIT1();
        } else {
            CP_WAIT0();
        }
        __syncthreads();

        const char* st = smem + cur * STAGE_B;
#pragma unroll
        for (int kk = 0; kk < 2; ++kk) {
            const int kbyte = kk * 32 + tig * 4;

            uint32_t afh[2][4], afl[2][4];
#pragma unroll
            for (int ms = 0; ms < 2; ++ms) {
                const char* ar = st + (wm * 32 + ms * 16 + g) * ROWB + kbyte;
                afh[ms][0] = *(const uint32_t*)(ar + OFF_AH);
                afh[ms][1] = *(const uint32_t*)(ar + OFF_AH + 8 * ROWB);
                afh[ms][2] = *(const uint32_t*)(ar + OFF_AH + 16);
                afh[ms][3] = *(const uint32_t*)(ar + OFF_AH + 8 * ROWB + 16);
                afl[ms][0] = *(const uint32_t*)(ar + OFF_AL);
                afl[ms][1] = *(const uint32_t*)(ar + OFF_AL + 8 * ROWB);
                afl[ms][2] = *(const uint32_t*)(ar + OFF_AL + 16);
                afl[ms][3] = *(const uint32_t*)(ar + OFF_AL + 8 * ROWB + 16);
            }
#pragma unroll
            for (int ns = 0; ns < 8; ++ns) {
                const char* br = st + (wn * 64 + ns * 8 + g) * ROWB + kbyte;
                uint32_t bfh[2];
                bfh[0] = *(const uint32_t*)(br + OFF_BH);
                bfh[1] = *(const uint32_t*)(br + OFF_BH + 16);
#pragma unroll
                for (int ms = 0; ms < 2; ++ms) {
                    mma16816(acc[ms][ns], afh[ms], bfh);
                    mma16816(acc[ms][ns], afl[ms], bfh);
                }
            }
        }
        __syncthreads();
    }

    // Epilogue
#pragma unroll
    for (int ms = 0; ms < 2; ++ms) {
        const int row = bm + wm * 32 + ms * 16 + g;
#pragma unroll
        for (int ns = 0; ns < 8; ++ns) {
            const int col = bn + wn * 64 + ns * 8 + tig * 2;
            *(float2*)&C[(size_t)row * Ncols + col] =
                make_float2(acc[ms][ns][0], acc[ms][ns][1]);
            *(float2*)&C[(size_t)(row + 8) * Ncols + col] =
                make_float2(acc[ms][ns][2], acc[ms][ns][3]);
        }
    }
}

// ---------------------------------------------------------------------------
// RoPE in place on q and k sections (tables)
// ---------------------------------------------------------------------------
__global__ __launch_bounds__(256) void rope_kernel(float* __restrict__ qkv)
{
    int idx = blockIdx.x * 256 + threadIdx.x;   // < 4194304
    int j = idx & 63;
    int h = (idx >> 6) & 15;
    int m = idx >> 10;
    int t = m & (TT - 1);

    float c = g_cos[t * 64 + j];
    float s = g_sin[t * 64 + j];

    size_t base = (size_t)m * NQKV + h * HD + j;
    float q1 = qkv[base];
    float q2 = qkv[base + 64];
    qkv[base]      = q1 * c - q2 * s;
    qkv[base + 64] = q2 * c + q1 * s;

    size_t kb = base + INNER;
    float k1 = qkv[kb];
    float k2 = qkv[kb + 64];
    qkv[kb]      = k1 * c - k2 * s;
    qkv[kb + 64] = k2 * c + k1 * s;
}

// ---------------------------------------------------------------------------
// Causal flash attention, CTA-tiled (known-good).
// CTA = 16 q rows (4 warps x 4 rows), K/V staged in smem in 32-k blocks.
// ---------------------------------------------------------------------------
#define AT_ROWS 16

__global__ __launch_bounds__(128) void attn_kernel(
    const float* __restrict__ qkv, float* __restrict__ outb)
{
    __shared__ float4 Qs4[32][AT_ROWS];   // [d4][r]
    __shared__ float4 KsT4[32][33];       // [d4][kcol] padded
    __shared__ float4 Vs4[32][33];        // [k][d4]    padded
    __shared__ float  Ps[32][AT_ROWS + 1];// [k][r]     padded

    const int tid  = threadIdx.x;
    const int lane = tid & 31;
    const int w    = tid >> 5;
    const int w4   = w * 4;
    const int b    = blockIdx.y >> 4;
    const int h    = blockIdx.y & 15;
    const int qt   = (int)(gridDim.x - 1 - blockIdx.x);
    const int q0   = qt * AT_ROWS;

    const float scale = 0.08838834764831845f;
    const float* base = qkv + (size_t)(b * TT) * NQKV + h * HD;
    const float* kb_  = base + INNER;
    const float* vb_  = base + 2 * INNER;

#pragma unroll
    for (int i = 0; i < 4; ++i) {
        int idx = tid + i * 128;
        int r   = idx >> 5;
        int d4  = idx & 31;
        float4 v = *(const float4*)(base + (size_t)(q0 + r) * NQKV + d4 * 4);
        v.x *= scale; v.y *= scale; v.z *= scale; v.w *= scale;
        Qs4[d4][r] = v;
    }

    float mr[4], lr[4];
    float4 o[4];
#pragma unroll
    for (int r = 0; r < 4; ++r) {
        mr[r] = -1.0e30f; lr[r] = 0.0f;
        o[r] = make_float4(0.f, 0.f, 0.f, 0.f);
    }

    const int nkb = (q0 + AT_ROWS + 31) >> 5;

    for (int kb = 0; kb < nkb; ++kb) {
        __syncthreads();
        const int k0 = kb * 32;
#pragma unroll
        for (int i = 0; i < 8; ++i) {
            int idx = tid + i * 128;
            int kr  = idx >> 5;
            int d4  = idx & 31;
            KsT4[d4][kr] = *(const float4*)(kb_ + (size_t)(k0 + kr) * NQKV + d4 * 4);
            Vs4[kr][d4]  = *(const float4*)(vb_ + (size_t)(k0 + kr) * NQKV + d4 * 4);
        }
        __syncthreads();

        float s[4] = {0.f, 0.f, 0.f, 0.f};
#pragma unroll 4
        for (int d4 = 0; d4 < 32; ++d4) {
            float4 kd = KsT4[d4][lane];
#pragma unroll
            for (int r = 0; r < 4; ++r) {
                float4 qv = Qs4[d4][w4 + r];
                s[r] = fmaf(qv.x, kd.x, s[r]);
                s[r] = fmaf(qv.y, kd.y, s[r]);
                s[r] = fmaf(qv.z, kd.z, s[r]);
                s[r] = fmaf(qv.w, kd.w, s[r]);
            }
        }
        const int kg = k0 + lane;
#pragma unroll
        for (int r = 0; r < 4; ++r)
            if (kg > q0 + w4 + r) s[r] = -1.0e30f;

#pragma unroll
        for (int r = 0; r < 4; ++r) {
            float bm = s[r];
            bm = fmaxf(bm, __shfl_xor_sync(0xffffffffu, bm, 1));
            bm = fmaxf(bm, __shfl_xor_sync(0xffffffffu, bm, 2));
            bm = fmaxf(bm, __shfl_xor_sync(0xffffffffu, bm, 4));
            bm = fmaxf(bm, __shfl_xor_sync(0xffffffffu, bm, 8));
            bm = fmaxf(bm, __shfl_xor_sync(0xffffffffu, bm, 16));
            float mn    = fmaxf(mr[r], bm);
            float alpha = __expf(mr[r] - mn);
            float p     = __expf(s[r] - mn);
            mr[r] = mn;
            float ps = p;
            ps += __shfl_xor_sync(0xffffffffu, ps, 1);
            ps += __shfl_xor_sync(0xffffffffu, ps, 2);
            ps += __shfl_xor_sync(0xffffffffu, ps, 4);
            ps += __shfl_xor_sync(0xffffffffu, ps, 8);
            ps += __shfl_xor_sync(0xffffffffu, ps, 16);
            lr[r] = lr[r] * alpha + ps;
            o[r].x *= alpha; o[r].y *= alpha; o[r].z *= alpha; o[r].w *= alpha;
            Ps[lane][w4 + r] = p;
        }
        __syncwarp();

#pragma unroll 4
        for (int k = 0; k < 32; ++k) {
            float4 vv = Vs4[k][lane];
#pragma unroll
            for (int r = 0; r < 4; ++r) {
                float p = Ps[k][w4 + r];
                o[r].x = fmaf(p, vv.x, o[r].x);
                o[r].y = fmaf(p, vv.y, o[r].y);
                o[r].z = fmaf(p, vv.z, o[r].z);
                o[r].w = fmaf(p, vv.w, o[r].w);
            }
        }
    }

#pragma unroll
    for (int r = 0; r < 4; ++r) {
        float inv = 1.0f / lr[r];
        float4 v = make_float4(o[r].x * inv, o[r].y * inv,
                               o[r].z * inv, o[r].w * inv);
        *(float4*)(outb + (size_t)(b * TT + q0 + w4 + r) * INNER
                   + h * HD + lane * 4) = v;
    }
}

// ---------------------------------------------------------------------------
// Entry point
// ---------------------------------------------------------------------------
extern "C" void kernel_launch(void* const* d_in, const int* in_sizes, int n_in,
                              void* d_out, int out_size)
{
    (void)out_size;
    const int NX = BB * TT * DIMM;   // 8388608
    const int NW = DIMM * NQKV;      // 12582912
    const int NO = INNER * DIMM;     // 4194304

    const float* x     = nullptr;
    const float* w_qkv = nullptr;
    const float* w_out = nullptr;
    for (int i = 0; i < n_in; ++i) {
        int sz = in_sizes[i];
        if      (sz == NX || sz == NX * 4) x     = (const float*)d_in[i];
        else if (sz == NW || sz == NW * 4) w_qkv = (const float*)d_in[i];
        else if (sz == NO || sz == NO * 4) w_out = (const float*)d_in[i];
    }
    if (!x || !w_qkv || !w_out) {
        x     = (const float*)d_in[0];
        w_qkv = (const float*)d_in[1];
        w_out = (const float*)d_in[2];
    }

    float* out = (float*)d_out;

    float *qkv_p, *attn_p;
    __half *ah, *al, *bh;
    cudaGetSymbolAddress((void**)&qkv_p,  g_qkv);
    cudaGetSymbolAddress((void**)&attn_p, g_attn);
    cudaGetSymbolAddress((void**)&ah, gA_hi);
    cudaGetSymbolAddress((void**)&al, gA_lo);
    cudaGetSymbolAddress((void**)&bh, gB_hi);

    cudaFuncSetAttribute(gemm_fp16x2,
                         cudaFuncAttributeMaxDynamicSharedMemorySize, GEMM_SMEM);

    // 1. RoPE tables
    table_kernel<<<(TT * 64) / 256, 256>>>();

    // 2. Split x -> fp16 hi/lo; transpose w_qkv -> fp16
    conv_split<<<NX / 1024, 256>>>(x, ah, al);
    conv_T<<<dim3(NQKV / 32, DIMM / 32), dim3(32, 8)>>>(w_qkv, bh, DIMM, NQKV);

    // 3. QKV projection (fp16x2, 2 MMAs per sub-tile)
    gemm_fp16x2<<<dim3(NQKV / 128, MROWS / 128), 256, GEMM_SMEM>>>(
        ah, al, bh, qkv_p, DIMM, NQKV);

    // 4. RoPE in place
    rope_kernel<<<(MROWS * HEADS * 64) / 256, 256>>>(qkv_p);

    // 5. Causal flash attention
    attn_kernel<<<dim3(TT / AT_ROWS, BB * HEADS), 128>>>(qkv_p, attn_p);

    // 6. Split attn output + transpose w_out; out projection
    conv_split<<<(MROWS * INNER) / 1024, 256>>>(attn_p, ah, al);
    conv_T<<<dim3(DIMM / 32, INNER / 32), dim3(32, 8)>>>(w_out, bh, INNER, DIMM);
    gemm_fp16x2<<<dim3(DIMM / 128, MROWS / 128), 256, GEMM_SMEM>>>(
        ah, al, bh, out, INNER, DIMM);
}

// round 14
// speedup vs baseline: 7.3776x; 1.9080x over previous
#include <cuda_runtime.h>
#include <cuda_fp16.h>
#include <math.h>
#include <stdint.h>

#define TT    2048
#define BB    2
#define DIMM  2048
#define HEADS 16
#define HD    128
#define INNER 2048
#define NQKV  6144
#define MROWS 4096   // B*T

// ---------------------------------------------------------------------------
// Scratch (device globals; no allocations allowed)
// ---------------------------------------------------------------------------
__device__ float g_qkv[(size_t)MROWS * NQKV];   // [4096, 6144] q|k|v (fp32)
__device__ float g_attn[(size_t)MROWS * INNER]; // [4096, 2048]
__device__ float g_cos[TT * 64];
__device__ float g_sin[TT * 64];
// fp16 GEMM operand buffers
__device__ __half gA_hi[(size_t)MROWS * DIMM];
__device__ __half gA_lo[(size_t)MROWS * DIMM];
__device__ __half gB_hi[(size_t)NQKV * DIMM];   // [N,K] transposed
// fp16 attention operand buffers
__device__ __half gQh[(size_t)MROWS * INNER];
__device__ __half gQl[(size_t)MROWS * INNER];
__device__ __half gKh[(size_t)MROWS * INNER];
__device__ __half gKl[(size_t)MROWS * INNER];
__device__ __half gVt[(size_t)BB * HEADS * HD * TT];  // [bh][d][t]

// ---------------------------------------------------------------------------
// Portable PTX helpers (sm_80+): cp.async + mma.sync fp16
// ---------------------------------------------------------------------------
__device__ __forceinline__ uint32_t smem_u32(const void* p) {
    uint32_t a;
    asm("{ .reg .u64 t; cvta.to.shared.u64 t, %1; cvt.u32.u64 %0, t; }"
        : "=r"(a) : "l"(p));
    return a;
}
__device__ __forceinline__ void cp16(uint32_t saddr, const void* g) {
    asm volatile("cp.async.ca.shared.global [%0], [%1], 16;"
                 :: "r"(saddr), "l"(g) : "memory");
}
#define CP_COMMIT() asm volatile("cp.async.commit_group;" ::: "memory")
#define CP_WAIT0()  asm volatile("cp.async.wait_group 0;" ::: "memory")
#define CP_WAIT1()  asm volatile("cp.async.wait_group 1;" ::: "memory")

__device__ __forceinline__ void mma16816(float* c, const uint32_t* a,
                                         const uint32_t* b) {
    asm volatile(
        "mma.sync.aligned.m16n8k16.row.col.f32.f16.f16.f32 "
        "{%0,%1,%2,%3}, {%4,%5,%6,%7}, {%8,%9}, {%0,%1,%2,%3};"
        : "+f"(c[0]), "+f"(c[1]), "+f"(c[2]), "+f"(c[3])
        : "r"(a[0]), "r"(a[1]), "r"(a[2]), "r"(a[3]), "r"(b[0]), "r"(b[1]));
}
__device__ __forceinline__ uint32_t packh2(float lo, float hi) {
    __half2 h = __floats2half2_rn(lo, hi);
    return *(uint32_t*)&h;
}

// ---------------------------------------------------------------------------
// RoPE cos/sin tables in fp64
// ---------------------------------------------------------------------------
__global__ void table_kernel() {
    int idx = blockIdx.x * 256 + threadIdx.x;
    int j = idx & 63;
    int t = idx >> 6;
    double inv = exp(-log(10000.0) * (double)j / 64.0);
    double ang = (double)t * inv;
    g_cos[idx] = (float)cos(ang);
    g_sin[idx] = (float)sin(ang);
}

// ---------------------------------------------------------------------------
// fp32 -> fp16 hi/lo split (GEMM A operand)
// ---------------------------------------------------------------------------
__global__ __launch_bounds__(256) void conv_split(
    const float* __restrict__ src, __half* __restrict__ hi,
    __half* __restrict__ lo)
{
    int i = blockIdx.x * 256 + threadIdx.x;
    float4 v = ((const float4*)src)[i];
    float vv[4] = {v.x, v.y, v.z, v.w};
#pragma unroll
    for (int j = 0; j < 4; ++j) {
        __half h = __float2half(vv[j]);
        hi[i * 4 + j] = h;
        lo[i * 4 + j] = __float2half(vv[j] - __half2float(h));
    }
}

// ---------------------------------------------------------------------------
// fp32 [K,N] -> transposed single fp16 [N,K] (GEMM B operand)
// ---------------------------------------------------------------------------
__global__ __launch_bounds__(256) void conv_T(
    const float* __restrict__ src, __half* __restrict__ hiT, int K, int N)
{
    __shared__ float tile[32][33];
    int n0 = blockIdx.x * 32, k0 = blockIdx.y * 32;
    int tx = threadIdx.x, ty = threadIdx.y;
#pragma unroll
    for (int j = 0; j < 4; ++j)
        tile[ty + 8 * j][tx] = src[(size_t)(k0 + ty + 8 * j) * N + n0 + tx];
    __syncthreads();
#pragma unroll
    for (int j = 0; j < 4; ++j) {
        float v = tile[tx][ty + 8 * j];
        hiT[(size_t)(n0 + ty + 8 * j) * K + k0 + tx] = __float2half(v);
    }
}

// ---------------------------------------------------------------------------
// mma.sync fp16x2 GEMM (unchanged, validated).
// ---------------------------------------------------------------------------
#define KC       32
#define ROWB     80
#define A_TILE_B (128 * ROWB)
#define OFF_AH   0
#define OFF_AL   A_TILE_B
#define OFF_BH   (2 * A_TILE_B)
#define STAGE_B  (3 * A_TILE_B)
#define NSTAGE   2
#define GEMM_SMEM (NSTAGE * STAGE_B)

__device__ __forceinline__ void load_chunk(
    uint32_t sbase,
    const __half* __restrict__ Ah, const __half* __restrict__ Al,
    const __half* __restrict__ Bh,
    int bm, int bn, int kc, int Kd, int tid)
{
    const int r = tid >> 1;
    const int s = (tid & 1) * 2;
    const size_t ga = (size_t)(bm + r) * Kd + kc * KC + s * 8;
    const size_t gb = (size_t)(bn + r) * Kd + kc * KC + s * 8;
    const uint32_t srow = sbase + r * ROWB + s * 16;
    cp16(srow + OFF_AH,      Ah + ga);
    cp16(srow + OFF_AH + 16, Ah + ga + 8);
    cp16(srow + OFF_AL,      Al + ga);
    cp16(srow + OFF_AL + 16, Al + ga + 8);
    cp16(srow + OFF_BH,      Bh + gb);
    cp16(srow + OFF_BH + 16, Bh + gb + 8);
}

__global__ __launch_bounds__(256, 2) void gemm_fp16x2(
    const __half* __restrict__ Ah, const __half* __restrict__ Al,
    const __half* __restrict__ Bh,
    float* __restrict__ C, int Kd, int Ncols)
{
    extern __shared__ char smem[];
    const uint32_t sb = smem_u32(smem);
    const int tid  = threadIdx.x;
    const int wid  = tid >> 5;
    const int lane = tid & 31;
    const int g    = lane >> 2;
    const int tig  = lane & 3;
    const int wm   = wid & 3;
    const int wn   = wid >> 2;
    const int bm   = blockIdx.y * 128;
    const int bn   = blockIdx.x * 128;

    float acc[2][8][4];
#pragma unroll
    for (int ms = 0; ms < 2; ++ms)
#pragma unroll
        for (int ns = 0; ns < 8; ++ns)
#pragma unroll
            for (int q = 0; q < 4; ++q) acc[ms][ns][q] = 0.0f;

    const int NT = Kd / KC;

    load_chunk(sb, Ah, Al, Bh, bm, bn, 0, Kd, tid);
    CP_COMMIT();

    for (int kc = 0; kc < NT; ++kc) {
        const int cur = kc & 1;
        if (kc + 1 < NT) {
            load_chunk(sb + (cur ^ 1) * STAGE_B, Ah, Al, Bh,
                       bm, bn, kc + 1, Kd, tid);
            CP_COMMIT();
            CP_WAIT1();
        } else {
            CP_WAIT0();
        }
        __syncthreads();

        const char* st = smem + cur * STAGE_B;
#pragma unroll
        for (int kk = 0; kk < 2; ++kk) {
            const int kbyte = kk * 32 + tig * 4;

            uint32_t afh[2][4], afl[2][4];
#pragma unroll
            for (int ms = 0; ms < 2; ++ms) {
                const char* ar = st + (wm * 32 + ms * 16 + g) * ROWB + kbyte;
                afh[ms][0] = *(const uint32_t*)(ar + OFF_AH);
                afh[ms][1] = *(const uint32_t*)(ar + OFF_AH + 8 * ROWB);
                afh[ms][2] = *(const uint32_t*)(ar + OFF_AH + 16);
                afh[ms][3] = *(const uint32_t*)(ar + OFF_AH + 8 * ROWB + 16);
                afl[ms][0] = *(const uint32_t*)(ar + OFF_AL);
                afl[ms][1] = *(const uint32_t*)(ar + OFF_AL + 8 * ROWB);
                afl[ms][2] = *(const uint32_t*)(ar + OFF_AL + 16);
                afl[ms][3] = *(const uint32_t*)(ar + OFF_AL + 8 * ROWB + 16);
            }
#pragma unroll
            for (int ns = 0; ns < 8; ++ns) {
                const char* br = st + (wn * 64 + ns * 8 + g) * ROWB + kbyte;
                uint32_t bfh[2];
                bfh[0] = *(const uint32_t*)(br + OFF_BH);
                bfh[1] = *(const uint32_t*)(br + OFF_BH + 16);
#pragma unroll
                for (int ms = 0; ms < 2; ++ms) {
                    mma16816(acc[ms][ns], afh[ms], bfh);
                    mma16816(acc[ms][ns], afl[ms], bfh);
                }
            }
        }
        __syncthreads();
    }

#pragma unroll
    for (int ms = 0; ms < 2; ++ms) {
        const int row = bm + wm * 32 + ms * 16 + g;
#pragma unroll
        for (int ns = 0; ns < 8; ++ns) {
            const int col = bn + wn * 64 + ns * 8 + tig * 2;
            *(float2*)&C[(size_t)row * Ncols + col] =
                make_float2(acc[ms][ns][0], acc[ms][ns][1]);
            *(float2*)&C[(size_t)(row + 8) * Ncols + col] =
                make_float2(acc[ms][ns][2], acc[ms][ns][3]);
        }
    }
}

// ---------------------------------------------------------------------------
// RoPE + fp16 split conversion for Q (pre-scaled) and K.
// ---------------------------------------------------------------------------
__global__ __launch_bounds__(256) void rope_conv(
    const float* __restrict__ qkv,
    __half* __restrict__ Qh, __half* __restrict__ Ql,
    __half* __restrict__ Kh, __half* __restrict__ Kl)
{
    int idx = blockIdx.x * 256 + threadIdx.x;   // < 4194304
    int j = idx & 63;
    int h = (idx >> 6) & 15;
    int m = idx >> 10;
    int t = m & (TT - 1);
    float c = g_cos[t * 64 + j];
    float s = g_sin[t * 64 + j];
    const float scale = 0.08838834764831845f;

    size_t ib = (size_t)m * NQKV + h * HD + j;
    float q1 = qkv[ib], q2 = qkv[ib + 64];
    float k1 = qkv[ib + INNER], k2 = qkv[ib + INNER + 64];
    float qa = (q1 * c - q2 * s) * scale;
    float qb = (q2 * c + q1 * s) * scale;
    float ka = k1 * c - k2 * s;
    float kb = k2 * c + k1 * s;

    size_t ob = (size_t)m * INNER + h * HD + j;
    __half hh;
    hh = __float2half(qa); Qh[ob] = hh;
    Ql[ob] = __float2half(qa - __half2float(hh));
    hh = __float2half(qb); Qh[ob + 64] = hh;
    Ql[ob + 64] = __float2half(qb - __half2float(hh));
    hh = __float2half(ka); Kh[ob] = hh;
    Kl[ob] = __float2half(ka - __half2float(hh));
    hh = __float2half(kb); Kh[ob + 64] = hh;
    Kl[ob + 64] = __float2half(kb - __half2float(hh));
}

// ---------------------------------------------------------------------------
// V: fp32 strided [m][2*INNER + h*HD + d] -> fp16 transposed [bh][d][t]
// ---------------------------------------------------------------------------
__global__ __launch_bounds__(256) void conv_vT(
    const float* __restrict__ qkv, __half* __restrict__ Vt)
{
    __shared__ float tile[32][33];
    int t0 = blockIdx.x * 32;
    int d0 = blockIdx.y * 32;
    int bh = blockIdx.z;
    int b = bh >> 4, h = bh & 15;
    int tx = threadIdx.x, ty = threadIdx.y;
    const float* src = qkv + (size_t)(b * TT) * NQKV + 2 * INNER + h * HD;
#pragma unroll
    for (int j = 0; j < 4; ++j)
        tile[ty + 8 * j][tx] = src[(size_t)(t0 + ty + 8 * j) * NQKV + d0 + tx];
    __syncthreads();
    __half* dst = Vt + (size_t)bh * HD * TT;
#pragma unroll
    for (int j = 0; j < 4; ++j)
        dst[(size_t)(d0 + ty + 8 * j) * TT + t0 + tx] =
            __float2half(tile[tx][ty + 8 * j]);
}

// ---------------------------------------------------------------------------
// Tensor-core causal flash attention.
// CTA = 64 q rows (4 warps x 16 rows), k-blocks of 64.
// Scores: (Qh+Ql)(Kh+Kl) -> 3 MMAs per sub-tile (near-exact).
// PV: fp16 P x fp16 V (Vt pre-transposed [d][t]).
// ---------------------------------------------------------------------------
#define QROWB 272   // 128 fp16 = 256B + 16 pad (bank-conflict-free)
#define VROWB 144   // 64 fp16 = 128B + 16 pad
#define SQH 0
#define SQL 17408
#define SKH 34816
#define SKL 52224
#define SVT 69632
#define ATTN_SMEM 88064

__global__ __launch_bounds__(128, 2) void attn_fa(
    const __half* __restrict__ Qh_, const __half* __restrict__ Ql_,
    const __half* __restrict__ Kh_, const __half* __restrict__ Kl_,
    const __half* __restrict__ Vt_, float* __restrict__ outb)
{
    extern __shared__ char sm_[];
    const uint32_t sb = smem_u32(sm_);
    const char* smc = sm_;
    const int tid  = threadIdx.x;
    const int lane = tid & 31;
    const int w    = tid >> 5;
    const int g    = lane >> 2;
    const int tig  = lane & 3;
    const int qt   = (int)(gridDim.x - 1 - blockIdx.x);   // heavy first
    const int q0   = qt * 64;
    const int bh   = blockIdx.y;
    const int b    = bh >> 4;
    const int h    = bh & 15;

    // Stage Q hi/lo (64 rows x 16 x 16B)
    const size_t qrow0 = (size_t)(b * TT + q0) * INNER + h * HD;
#pragma unroll
    for (int it = 0; it < 8; ++it) {
        int seg = it * 128 + tid;
        int r = seg >> 4, s2 = seg & 15;
        cp16(sb + SQH + r * QROWB + s2 * 16, Qh_ + qrow0 + (size_t)r * INNER + s2 * 8);
        cp16(sb + SQL + r * QROWB + s2 * 16, Ql_ + qrow0 + (size_t)r * INNER + s2 * 8);
    }
    CP_COMMIT();

    float o[16][4];
#pragma unroll
    for (int nt = 0; nt < 16; ++nt)
#pragma unroll
        for (int q = 0; q < 4; ++q) o[nt][q] = 0.0f;
    float m0 = -1.0e30f, m1 = -1.0e30f, l0 = 0.0f, l1 = 0.0f;

    for (int kb = 0; kb <= qt; ++kb) {
        const int k0 = kb * 64;
        const size_t krow0 = (size_t)(b * TT + k0) * INNER + h * HD;
        const size_t vrow0 = (size_t)bh * HD * TT + k0;
#pragma unroll
        for (int it = 0; it < 8; ++it) {
            int seg = it * 128 + tid;
            int r = seg >> 4, s2 = seg & 15;
            cp16(sb + SKH + r * QROWB + s2 * 16, Kh_ + krow0 + (size_t)r * INNER + s2 * 8);
            cp16(sb + SKL + r * QROWB + s2 * 16, Kl_ + krow0 + (size_t)r * INNER + s2 * 8);
            int d = seg >> 3, s3 = seg & 7;
            cp16(sb + SVT + d * VROWB + s3 * 16, Vt_ + vrow0 + (size_t)d * TT + s3 * 8);
        }
        CP_COMMIT();
        CP_WAIT0();
        __syncthreads();

        // ---- S = Q K^T ----
        float sf[8][4];
#pragma unroll
        for (int ns = 0; ns < 8; ++ns)
#pragma unroll
            for (int q = 0; q < 4; ++q) sf[ns][q] = 0.0f;

#pragma unroll
        for (int ch = 0; ch < 8; ++ch) {
            const int kbyte = ch * 32 + tig * 4;
            const char* aq = smc + (w * 16 + g) * QROWB + kbyte;
            uint32_t ah4[4], al4[4];
            ah4[0] = *(const uint32_t*)(aq + SQH);
            ah4[1] = *(const uint32_t*)(aq + SQH + 8 * QROWB);
            ah4[2] = *(const uint32_t*)(aq + SQH + 16);
            ah4[3] = *(const uint32_t*)(aq + SQH + 8 * QROWB + 16);
            al4[0] = *(const uint32_t*)(aq + SQL);
            al4[1] = *(const uint32_t*)(aq + SQL + 8 * QROWB);
            al4[2] = *(const uint32_t*)(aq + SQL + 16);
            al4[3] = *(const uint32_t*)(aq + SQL + 8 * QROWB + 16);
#pragma unroll
            for (int ns = 0; ns < 8; ++ns) {
                const char* bk = smc + (ns * 8 + g) * QROWB + kbyte;
                uint32_t bh2[2], bl2[2];
                bh2[0] = *(const uint32_t*)(bk + SKH);
                bh2[1] = *(const uint32_t*)(bk + SKH + 16);
                bl2[0] = *(const uint32_t*)(bk + SKL);
                bl2[1] = *(const uint32_t*)(bk + SKL + 16);
                mma16816(sf[ns], ah4, bh2);
                mma16816(sf[ns], ah4, bl2);
                mma16816(sf[ns], al4, bh2);
            }
        }

        // causal mask on the diagonal block (k0 == q0)
        if (kb == qt) {
#pragma unroll
            for (int ns = 0; ns < 8; ++ns) {
                int cc = ns * 8 + 2 * tig;
                int rr = w * 16 + g;
                if (cc     > rr)     sf[ns][0] = -1.0e30f;
                if (cc + 1 > rr)     sf[ns][1] = -1.0e30f;
                if (cc     > rr + 8) sf[ns][2] = -1.0e30f;
                if (cc + 1 > rr + 8) sf[ns][3] = -1.0e30f;
            }
        }

        // ---- online softmax (rows g and g+8) ----
        float rm0 = -1.0e30f, rm1 = -1.0e30f;
#pragma unroll
        for (int ns = 0; ns < 8; ++ns) {
            rm0 = fmaxf(rm0, fmaxf(sf[ns][0], sf[ns][1]));
            rm1 = fmaxf(rm1, fmaxf(sf[ns][2], sf[ns][3]));
        }
        rm0 = fmaxf(rm0, __shfl_xor_sync(0xffffffffu, rm0, 1));
        rm0 = fmaxf(rm0, __shfl_xor_sync(0xffffffffu, rm0, 2));
        rm1 = fmaxf(rm1, __shfl_xor_sync(0xffffffffu, rm1, 1));
        rm1 = fmaxf(rm1, __shfl_xor_sync(0xffffffffu, rm1, 2));
        float mn0 = fmaxf(m0, rm0), mn1 = fmaxf(m1, rm1);
        float a0 = __expf(m0 - mn0), a1 = __expf(m1 - mn1);
        m0 = mn0; m1 = mn1;

        float rs0 = 0.0f, rs1 = 0.0f;
#pragma unroll
        for (int ns = 0; ns < 8; ++ns) {
            sf[ns][0] = __expf(sf[ns][0] - mn0);
            sf[ns][1] = __expf(sf[ns][1] - mn0);
            sf[ns][2] = __expf(sf[ns][2] - mn1);
            sf[ns][3] = __expf(sf[ns][3] - mn1);
            rs0 += sf[ns][0] + sf[ns][1];
            rs1 += sf[ns][2] + sf[ns][3];
        }
        rs0 += __shfl_xor_sync(0xffffffffu, rs0, 1);
        rs0 += __shfl_xor_sync(0xffffffffu, rs0, 2);
        rs1 += __shfl_xor_sync(0xffffffffu, rs1, 1);
        rs1 += __shfl_xor_sync(0xffffffffu, rs1, 2);
        l0 = l0 * a0 + rs0;
        l1 = l1 * a1 + rs1;

#pragma unroll
        for (int nt = 0; nt < 16; ++nt) {
            o[nt][0] *= a0; o[nt][1] *= a0;
            o[nt][2] *= a1; o[nt][3] *= a1;
        }

        // pack P into fp16 A-fragments (k-chunks of 16 kv = S tiles 2j,2j+1)
        uint32_t pa[4][4];
#pragma unroll
        for (int j = 0; j < 4; ++j) {
            pa[j][0] = packh2(sf[2 * j][0],     sf[2 * j][1]);
            pa[j][1] = packh2(sf[2 * j][2],     sf[2 * j][3]);
            pa[j][2] = packh2(sf[2 * j + 1][0], sf[2 * j + 1][1]);
            pa[j][3] = packh2(sf[2 * j + 1][2], sf[2 * j + 1][3]);
        }

        // ---- O += P V ----
#pragma unroll
        for (int j = 0; j < 4; ++j) {
#pragma unroll
            for (int nt = 0; nt < 16; ++nt) {
                const char* bv = smc + SVT + (nt * 8 + g) * VROWB + j * 32 + tig * 4;
                uint32_t bv2[2];
                bv2[0] = *(const uint32_t*)(bv);
                bv2[1] = *(const uint32_t*)(bv + 16);
                mma16816(o[nt], pa[j], bv2);
            }
        }
        __syncthreads();   // protect K/V smem before next staging
    }

    // ---- normalize + write ----
    float i0 = 1.0f / l0, i1 = 1.0f / l1;
    const int r0 = q0 + w * 16 + g;
    const size_t ob = (size_t)(b * TT + r0) * INNER + h * HD;
#pragma unroll
    for (int nt = 0; nt < 16; ++nt) {
        int col = nt * 8 + 2 * tig;
        *(float2*)&outb[ob + col] =
            make_float2(o[nt][0] * i0, o[nt][1] * i0);
        *(float2*)&outb[ob + (size_t)8 * INNER + col] =
            make_float2(o[nt][2] * i1, o[nt][3] * i1);
    }
}

// ---------------------------------------------------------------------------
// Entry point
// ---------------------------------------------------------------------------
extern "C" void kernel_launch(void* const* d_in, const int* in_sizes, int n_in,
                              void* d_out, int out_size)
{
    (void)out_size;
    const int NX = BB * TT * DIMM;
    const int NW = DIMM * NQKV;
    const int NO = INNER * DIMM;

    const float* x     = nullptr;
    const float* w_qkv = nullptr;
    const float* w_out = nullptr;
    for (int i = 0; i < n_in; ++i) {
        int sz = in_sizes[i];
        if      (sz == NX || sz == NX * 4) x     = (const float*)d_in[i];
        else if (sz == NW || sz == NW * 4) w_qkv = (const float*)d_in[i];
        else if (sz == NO || sz == NO * 4) w_out = (const float*)d_in[i];
    }
    if (!x || !w_qkv || !w_out) {
        x     = (const float*)d_in[0];
        w_qkv = (const float*)d_in[1];
        w_out = (const float*)d_in[2];
    }

    float* out = (float*)d_out;

    float *qkv_p, *attn_p;
    __half *ah, *al, *bh;
    __half *qh, *ql, *kh, *kl, *vt;
    cudaGetSymbolAddress((void**)&qkv_p,  g_qkv);
    cudaGetSymbolAddress((void**)&attn_p, g_attn);
    cudaGetSymbolAddress((void**)&ah, gA_hi);
    cudaGetSymbolAddress((void**)&al, gA_lo);
    cudaGetSymbolAddress((void**)&bh, gB_hi);
    cudaGetSymbolAddress((void**)&qh, gQh);
    cudaGetSymbolAddress((void**)&ql, gQl);
    cudaGetSymbolAddress((void**)&kh, gKh);
    cudaGetSymbolAddress((void**)&kl, gKl);
    cudaGetSymbolAddress((void**)&vt, gVt);

    cudaFuncSetAttribute(gemm_fp16x2,
                         cudaFuncAttributeMaxDynamicSharedMemorySize, GEMM_SMEM);
    cudaFuncSetAttribute(attn_fa,
                         cudaFuncAttributeMaxDynamicSharedMemorySize, ATTN_SMEM);

    // 1. RoPE tables
    table_kernel<<<(TT * 64) / 256, 256>>>();

    // 2. GEMM operands; QKV projection
    conv_split<<<NX / 1024, 256>>>(x, ah, al);
    conv_T<<<dim3(NQKV / 32, DIMM / 32), dim3(32, 8)>>>(w_qkv, bh, DIMM, NQKV);
    gemm_fp16x2<<<dim3(NQKV / 128, MROWS / 128), 256, GEMM_SMEM>>>(
        ah, al, bh, qkv_p, DIMM, NQKV);

    // 3. RoPE + fp16 conversion for attention operands
    rope_conv<<<(MROWS * HEADS * 64) / 256, 256>>>(qkv_p, qh, ql, kh, kl);
    conv_vT<<<dim3(TT / 32, HD / 32, BB * HEADS), dim3(32, 8)>>>(qkv_p, vt);

    // 4. Tensor-core causal flash attention
    attn_fa<<<dim3(TT / 64, BB * HEADS), 128, ATTN_SMEM>>>(
        qh, ql, kh, kl, vt, attn_p);

    // 5. Out projection
    conv_split<<<(MROWS * INNER) / 1024, 256>>>(attn_p, ah, al);
    conv_T<<<dim3(DIMM / 32, INNER / 32), dim3(32, 8)>>>(w_out, bh, INNER, DIMM);
    gemm_fp16x2<<<dim3(DIMM / 128, MROWS / 128), 256, GEMM_SMEM>>>(
        ah, al, bh, out, INNER, DIMM);
}

// round 15
// speedup vs baseline: 9.8657x; 1.3373x over previous
#include <cuda_runtime.h>
#include <cuda_fp16.h>
#include <math.h>
#include <stdint.h>

#define TT    2048
#define BB    2
#define DIMM  2048
#define HEADS 16
#define HD    128
#define INNER 2048
#define NQKV  6144
#define MROWS 4096   // B*T

// ---------------------------------------------------------------------------
// Scratch (device globals; no allocations allowed)
// ---------------------------------------------------------------------------
__device__ float g_qkv[(size_t)MROWS * NQKV];   // [4096, 6144] q|k|v (fp32)
__device__ float g_attn[(size_t)MROWS * INNER]; // [4096, 2048]
__device__ float g_cos[TT * 64];
__device__ float g_sin[TT * 64];
// fp16 GEMM operand buffers (single-precision fp16 operands)
__device__ __half gA_h[(size_t)MROWS * DIMM];
__device__ __half gB_h[(size_t)NQKV * DIMM];    // [N,K] transposed
// fp16 attention operand buffers (hi/lo split kept for accuracy)
__device__ __half gQh[(size_t)MROWS * INNER];
__device__ __half gQl[(size_t)MROWS * INNER];
__device__ __half gKh[(size_t)MROWS * INNER];
__device__ __half gKl[(size_t)MROWS * INNER];
__device__ __half gVt[(size_t)BB * HEADS * HD * TT];  // [bh][d][t]

// ---------------------------------------------------------------------------
// Portable PTX helpers (sm_80+): cp.async + mma.sync fp16
// ---------------------------------------------------------------------------
__device__ __forceinline__ uint32_t smem_u32(const void* p) {
    uint32_t a;
    asm("{ .reg .u64 t; cvta.to.shared.u64 t, %1; cvt.u32.u64 %0, t; }"
        : "=r"(a) : "l"(p));
    return a;
}
__device__ __forceinline__ void cp16(uint32_t saddr, const void* g) {
    asm volatile("cp.async.ca.shared.global [%0], [%1], 16;"
                 :: "r"(saddr), "l"(g) : "memory");
}
#define CP_COMMIT() asm volatile("cp.async.commit_group;" ::: "memory")
#define CP_WAIT0()  asm volatile("cp.async.wait_group 0;" ::: "memory")
#define CP_WAIT1()  asm volatile("cp.async.wait_group 1;" ::: "memory")

__device__ __forceinline__ void mma16816(float* c, const uint32_t* a,
                                         const uint32_t* b) {
    asm volatile(
        "mma.sync.aligned.m16n8k16.row.col.f32.f16.f16.f32 "
        "{%0,%1,%2,%3}, {%4,%5,%6,%7}, {%8,%9}, {%0,%1,%2,%3};"
        : "+f"(c[0]), "+f"(c[1]), "+f"(c[2]), "+f"(c[3])
        : "r"(a[0]), "r"(a[1]), "r"(a[2]), "r"(a[3]), "r"(b[0]), "r"(b[1]));
}
__device__ __forceinline__ uint32_t packh2(float lo, float hi) {
    __half2 h = __floats2half2_rn(lo, hi);
    return *(uint32_t*)&h;
}

// ---------------------------------------------------------------------------
// RoPE cos/sin tables in fp64
// ---------------------------------------------------------------------------
__global__ void table_kernel() {
    int idx = blockIdx.x * 256 + threadIdx.x;
    int j = idx & 63;
    int t = idx >> 6;
    double inv = exp(-log(10000.0) * (double)j / 64.0);
    double ang = (double)t * inv;
    g_cos[idx] = (float)cos(ang);
    g_sin[idx] = (float)sin(ang);
}

// ---------------------------------------------------------------------------
// fp32 -> fp16 (GEMM A operand, single precision)
// ---------------------------------------------------------------------------
__global__ __launch_bounds__(256) void conv_h(
    const float* __restrict__ src, __half* __restrict__ dst)
{
    int i = blockIdx.x * 256 + threadIdx.x;
    float4 v = ((const float4*)src)[i];
    __half2 h0 = __floats2half2_rn(v.x, v.y);
    __half2 h1 = __floats2half2_rn(v.z, v.w);
    ((__half2*)dst)[i * 2]     = h0;
    ((__half2*)dst)[i * 2 + 1] = h1;
}

// ---------------------------------------------------------------------------
// fp32 [K,N] -> transposed single fp16 [N,K] (GEMM B operand)
// ---------------------------------------------------------------------------
__global__ __launch_bounds__(256) void conv_T(
    const float* __restrict__ src, __half* __restrict__ hiT, int K, int N)
{
    __shared__ float tile[32][33];
    int n0 = blockIdx.x * 32, k0 = blockIdx.y * 32;
    int tx = threadIdx.x, ty = threadIdx.y;
#pragma unroll
    for (int j = 0; j < 4; ++j)
        tile[ty + 8 * j][tx] = src[(size_t)(k0 + ty + 8 * j) * N + n0 + tx];
    __syncthreads();
#pragma unroll
    for (int j = 0; j < 4; ++j) {
        float v = tile[tx][ty + 8 * j];
        hiT[(size_t)(n0 + ty + 8 * j) * K + k0 + tx] = __float2half(v);
    }
}

// ---------------------------------------------------------------------------
// mma.sync pure-fp16 GEMM: 1 MMA per sub-tile.
// CTA: 128x128 tile, 256 threads = 8 warps (4M x 2N), warp tile 32x64.
// 2-stage cp.async pipeline, 2 CTAs/SM.
// ---------------------------------------------------------------------------
#define KC       32
#define ROWB     80
#define A_TILE_B (128 * ROWB)              // 10240
#define OFF_A    0
#define OFF_B    A_TILE_B                  // 10240
#define STAGE_B  (2 * A_TILE_B)            // 20480
#define GEMM_SMEM (2 * STAGE_B)            // 40960

__device__ __forceinline__ void load_chunk(
    uint32_t sbase,
    const __half* __restrict__ Ah, const __half* __restrict__ Bh,
    int bm, int bn, int kc, int Kd, int tid)
{
    const int r = tid >> 1;             // 0..127
    const int s = (tid & 1) * 2;        // 0 or 2 (16B segs within 64B row)
    const size_t ga = (size_t)(bm + r) * Kd + kc * KC + s * 8;
    const size_t gb = (size_t)(bn + r) * Kd + kc * KC + s * 8;
    const uint32_t srow = sbase + r * ROWB + s * 16;
    cp16(srow + OFF_A,      Ah + ga);
    cp16(srow + OFF_A + 16, Ah + ga + 8);
    cp16(srow + OFF_B,      Bh + gb);
    cp16(srow + OFF_B + 16, Bh + gb + 8);
}

__global__ __launch_bounds__(256, 2) void gemm_fp16(
    const __half* __restrict__ Ah, const __half* __restrict__ Bh,
    float* __restrict__ C, int Kd, int Ncols)
{
    extern __shared__ char smem[];
    const uint32_t sb = smem_u32(smem);
    const int tid  = threadIdx.x;
    const int wid  = tid >> 5;
    const int lane = tid & 31;
    const int g    = lane >> 2;
    const int tig  = lane & 3;
    const int wm   = wid & 3;           // M offset 32*wm
    const int wn   = wid >> 2;          // 0..1 -> N offset 64*wn
    const int bm   = blockIdx.y * 128;
    const int bn   = blockIdx.x * 128;

    float acc[2][8][4];
#pragma unroll
    for (int ms = 0; ms < 2; ++ms)
#pragma unroll
        for (int ns = 0; ns < 8; ++ns)
#pragma unroll
            for (int q = 0; q < 4; ++q) acc[ms][ns][q] = 0.0f;

    const int NT = Kd / KC;

    load_chunk(sb, Ah, Bh, bm, bn, 0, Kd, tid);
    CP_COMMIT();

    for (int kc = 0; kc < NT; ++kc) {
        const int cur = kc & 1;
        if (kc + 1 < NT) {
            load_chunk(sb + (cur ^ 1) * STAGE_B, Ah, Bh,
                       bm, bn, kc + 1, Kd, tid);
            CP_COMMIT();
            CP_WAIT1();
        } else {
            CP_WAIT0();
        }
        __syncthreads();

        const char* st = smem + cur * STAGE_B;
#pragma unroll
        for (int kk = 0; kk < 2; ++kk) {
            const int kbyte = kk * 32 + tig * 4;

            uint32_t af[2][4];
#pragma unroll
            for (int ms = 0; ms < 2; ++ms) {
                const char* ar = st + (wm * 32 + ms * 16 + g) * ROWB + kbyte;
                af[ms][0] = *(const uint32_t*)(ar + OFF_A);
                af[ms][1] = *(const uint32_t*)(ar + OFF_A + 8 * ROWB);
                af[ms][2] = *(const uint32_t*)(ar + OFF_A + 16);
                af[ms][3] = *(const uint32_t*)(ar + OFF_A + 8 * ROWB + 16);
            }
#pragma unroll
            for (int ns = 0; ns < 8; ++ns) {
                const char* br = st + (wn * 64 + ns * 8 + g) * ROWB + kbyte;
                uint32_t bf[2];
                bf[0] = *(const uint32_t*)(br + OFF_B);
                bf[1] = *(const uint32_t*)(br + OFF_B + 16);
#pragma unroll
                for (int ms = 0; ms < 2; ++ms)
                    mma16816(acc[ms][ns], af[ms], bf);
            }
        }
        __syncthreads();
    }

#pragma unroll
    for (int ms = 0; ms < 2; ++ms) {
        const int row = bm + wm * 32 + ms * 16 + g;
#pragma unroll
        for (int ns = 0; ns < 8; ++ns) {
            const int col = bn + wn * 64 + ns * 8 + tig * 2;
            *(float2*)&C[(size_t)row * Ncols + col] =
                make_float2(acc[ms][ns][0], acc[ms][ns][1]);
            *(float2*)&C[(size_t)(row + 8) * Ncols + col] =
                make_float2(acc[ms][ns][2], acc[ms][ns][3]);
        }
    }
}

// ---------------------------------------------------------------------------
// RoPE + fp16 split conversion for Q (pre-scaled) and K.
// ---------------------------------------------------------------------------
__global__ __launch_bounds__(256) void rope_conv(
    const float* __restrict__ qkv,
    __half* __restrict__ Qh, __half* __restrict__ Ql,
    __half* __restrict__ Kh, __half* __restrict__ Kl)
{
    int idx = blockIdx.x * 256 + threadIdx.x;   // < 4194304
    int j = idx & 63;
    int h = (idx >> 6) & 15;
    int m = idx >> 10;
    int t = m & (TT - 1);
    float c = g_cos[t * 64 + j];
    float s = g_sin[t * 64 + j];
    const float scale = 0.08838834764831845f;

    size_t ib = (size_t)m * NQKV + h * HD + j;
    float q1 = qkv[ib], q2 = qkv[ib + 64];
    float k1 = qkv[ib + INNER], k2 = qkv[ib + INNER + 64];
    float qa = (q1 * c - q2 * s) * scale;
    float qb = (q2 * c + q1 * s) * scale;
    float ka = k1 * c - k2 * s;
    float kb = k2 * c + k1 * s;

    size_t ob = (size_t)m * INNER + h * HD + j;
    __half hh;
    hh = __float2half(qa); Qh[ob] = hh;
    Ql[ob] = __float2half(qa - __half2float(hh));
    hh = __float2half(qb); Qh[ob + 64] = hh;
    Ql[ob + 64] = __float2half(qb - __half2float(hh));
    hh = __float2half(ka); Kh[ob] = hh;
    Kl[ob] = __float2half(ka - __half2float(hh));
    hh = __float2half(kb); Kh[ob + 64] = hh;
    Kl[ob + 64] = __float2half(kb - __half2float(hh));
}

// ---------------------------------------------------------------------------
// V: fp32 strided [m][2*INNER + h*HD + d] -> fp16 transposed [bh][d][t]
// ---------------------------------------------------------------------------
__global__ __launch_bounds__(256) void conv_vT(
    const float* __restrict__ qkv, __half* __restrict__ Vt)
{
    __shared__ float tile[32][33];
    int t0 = blockIdx.x * 32;
    int d0 = blockIdx.y * 32;
    int bh = blockIdx.z;
    int b = bh >> 4, h = bh & 15;
    int tx = threadIdx.x, ty = threadIdx.y;
    const float* src = qkv + (size_t)(b * TT) * NQKV + 2 * INNER + h * HD;
#pragma unroll
    for (int j = 0; j < 4; ++j)
        tile[ty + 8 * j][tx] = src[(size_t)(t0 + ty + 8 * j) * NQKV + d0 + tx];
    __syncthreads();
    __half* dst = Vt + (size_t)bh * HD * TT;
#pragma unroll
    for (int j = 0; j < 4; ++j)
        dst[(size_t)(d0 + ty + 8 * j) * TT + t0 + tx] =
            __float2half(tile[tx][ty + 8 * j]);
}

// ---------------------------------------------------------------------------
// Tensor-core causal flash attention (validated in R14, unchanged).
// CTA = 64 q rows (4 warps x 16 rows), k-blocks of 64.
// ---------------------------------------------------------------------------
#define QROWB 272
#define VROWB 144
#define SQH 0
#define SQL 17408
#define SKH 34816
#define SKL 52224
#define SVT 69632
#define ATTN_SMEM 88064

__global__ __launch_bounds__(128, 2) void attn_fa(
    const __half* __restrict__ Qh_, const __half* __restrict__ Ql_,
    const __half* __restrict__ Kh_, const __half* __restrict__ Kl_,
    const __half* __restrict__ Vt_, float* __restrict__ outb)
{
    extern __shared__ char sm_[];
    const uint32_t sb = smem_u32(sm_);
    const char* smc = sm_;
    const int tid  = threadIdx.x;
    const int lane = tid & 31;
    const int w    = tid >> 5;
    const int g    = lane >> 2;
    const int tig  = lane & 3;
    const int qt   = (int)(gridDim.x - 1 - blockIdx.x);   // heavy first
    const int q0   = qt * 64;
    const int bh   = blockIdx.y;
    const int b    = bh >> 4;
    const int h    = bh & 15;

    const size_t qrow0 = (size_t)(b * TT + q0) * INNER + h * HD;
#pragma unroll
    for (int it = 0; it < 8; ++it) {
        int seg = it * 128 + tid;
        int r = seg >> 4, s2 = seg & 15;
        cp16(sb + SQH + r * QROWB + s2 * 16, Qh_ + qrow0 + (size_t)r * INNER + s2 * 8);
        cp16(sb + SQL + r * QROWB + s2 * 16, Ql_ + qrow0 + (size_t)r * INNER + s2 * 8);
    }
    CP_COMMIT();

    float o[16][4];
#pragma unroll
    for (int nt = 0; nt < 16; ++nt)
#pragma unroll
        for (int q = 0; q < 4; ++q) o[nt][q] = 0.0f;
    float m0 = -1.0e30f, m1 = -1.0e30f, l0 = 0.0f, l1 = 0.0f;

    for (int kb = 0; kb <= qt; ++kb) {
        const int k0 = kb * 64;
        const size_t krow0 = (size_t)(b * TT + k0) * INNER + h * HD;
        const size_t vrow0 = (size_t)bh * HD * TT + k0;
#pragma unroll
        for (int it = 0; it < 8; ++it) {
            int seg = it * 128 + tid;
            int r = seg >> 4, s2 = seg & 15;
            cp16(sb + SKH + r * QROWB + s2 * 16, Kh_ + krow0 + (size_t)r * INNER + s2 * 8);
            cp16(sb + SKL + r * QROWB + s2 * 16, Kl_ + krow0 + (size_t)r * INNER + s2 * 8);
            int d = seg >> 3, s3 = seg & 7;
            cp16(sb + SVT + d * VROWB + s3 * 16, Vt_ + vrow0 + (size_t)d * TT + s3 * 8);
        }
        CP_COMMIT();
        CP_WAIT0();
        __syncthreads();

        float sf[8][4];
#pragma unroll
        for (int ns = 0; ns < 8; ++ns)
#pragma unroll
            for (int q = 0; q < 4; ++q) sf[ns][q] = 0.0f;

#pragma unroll
        for (int ch = 0; ch < 8; ++ch) {
            const int kbyte = ch * 32 + tig * 4;
            const char* aq = smc + (w * 16 + g) * QROWB + kbyte;
            uint32_t ah4[4], al4[4];
            ah4[0] = *(const uint32_t*)(aq + SQH);
            ah4[1] = *(const uint32_t*)(aq + SQH + 8 * QROWB);
            ah4[2] = *(const uint32_t*)(aq + SQH + 16);
            ah4[3] = *(const uint32_t*)(aq + SQH + 8 * QROWB + 16);
            al4[0] = *(const uint32_t*)(aq + SQL);
            al4[1] = *(const uint32_t*)(aq + SQL + 8 * QROWB);
            al4[2] = *(const uint32_t*)(aq + SQL + 16);
            al4[3] = *(const uint32_t*)(aq + SQL + 8 * QROWB + 16);
#pragma unroll
            for (int ns = 0; ns < 8; ++ns) {
                const char* bk = smc + (ns * 8 + g) * QROWB + kbyte;
                uint32_t bh2[2], bl2[2];
                bh2[0] = *(const uint32_t*)(bk + SKH);
                bh2[1] = *(const uint32_t*)(bk + SKH + 16);
                bl2[0] = *(const uint32_t*)(bk + SKL);
                bl2[1] = *(const uint32_t*)(bk + SKL + 16);
                mma16816(sf[ns], ah4, bh2);
                mma16816(sf[ns], ah4, bl2);
                mma16816(sf[ns], al4, bh2);
            }
        }

        if (kb == qt) {
#pragma unroll
            for (int ns = 0; ns < 8; ++ns) {
                int cc = ns * 8 + 2 * tig;
                int rr = w * 16 + g;
                if (cc     > rr)     sf[ns][0] = -1.0e30f;
                if (cc + 1 > rr)     sf[ns][1] = -1.0e30f;
                if (cc     > rr + 8) sf[ns][2] = -1.0e30f;
                if (cc + 1 > rr + 8) sf[ns][3] = -1.0e30f;
            }
        }

        float rm0 = -1.0e30f, rm1 = -1.0e30f;
#pragma unroll
        for (int ns = 0; ns < 8; ++ns) {
            rm0 = fmaxf(rm0, fmaxf(sf[ns][0], sf[ns][1]));
            rm1 = fmaxf(rm1, fmaxf(sf[ns][2], sf[ns][3]));
        }
        rm0 = fmaxf(rm0, __shfl_xor_sync(0xffffffffu, rm0, 1));
        rm0 = fmaxf(rm0, __shfl_xor_sync(0xffffffffu, rm0, 2));
        rm1 = fmaxf(rm1, __shfl_xor_sync(0xffffffffu, rm1, 1));
        rm1 = fmaxf(rm1, __shfl_xor_sync(0xffffffffu, rm1, 2));
        float mn0 = fmaxf(m0, rm0), mn1 = fmaxf(m1, rm1);
        float a0 = __expf(m0 - mn0), a1 = __expf(m1 - mn1);
        m0 = mn0; m1 = mn1;

        float rs0 = 0.0f, rs1 = 0.0f;
#pragma unroll
        for (int ns = 0; ns < 8; ++ns) {
            sf[ns][0] = __expf(sf[ns][0] - mn0);
            sf[ns][1] = __expf(sf[ns][1] - mn0);
            sf[ns][2] = __expf(sf[ns][2] - mn1);
            sf[ns][3] = __expf(sf[ns][3] - mn1);
            rs0 += sf[ns][0] + sf[ns][1];
            rs1 += sf[ns][2] + sf[ns][3];
        }
        rs0 += __shfl_xor_sync(0xffffffffu, rs0, 1);
        rs0 += __shfl_xor_sync(0xffffffffu, rs0, 2);
        rs1 += __shfl_xor_sync(0xffffffffu, rs1, 1);
        rs1 += __shfl_xor_sync(0xffffffffu, rs1, 2);
        l0 = l0 * a0 + rs0;
        l1 = l1 * a1 + rs1;

#pragma unroll
        for (int nt = 0; nt < 16; ++nt) {
            o[nt][0] *= a0; o[nt][1] *= a0;
            o[nt][2] *= a1; o[nt][3] *= a1;
        }

        uint32_t pa[4][4];
#pragma unroll
        for (int j = 0; j < 4; ++j) {
            pa[j][0] = packh2(sf[2 * j][0],     sf[2 * j][1]);
            pa[j][1] = packh2(sf[2 * j][2],     sf[2 * j][3]);
            pa[j][2] = packh2(sf[2 * j + 1][0], sf[2 * j + 1][1]);
            pa[j][3] = packh2(sf[2 * j + 1][2], sf[2 * j + 1][3]);
        }

#pragma unroll
        for (int j = 0; j < 4; ++j) {
#pragma unroll
            for (int nt = 0; nt < 16; ++nt) {
                const char* bv = smc + SVT + (nt * 8 + g) * VROWB + j * 32 + tig * 4;
                uint32_t bv2[2];
                bv2[0] = *(const uint32_t*)(bv);
                bv2[1] = *(const uint32_t*)(bv + 16);
                mma16816(o[nt], pa[j], bv2);
            }
        }
        __syncthreads();
    }

    float i0 = 1.0f / l0, i1 = 1.0f / l1;
    const int r0 = q0 + w * 16 + g;
    const size_t ob = (size_t)(b * TT + r0) * INNER + h * HD;
#pragma unroll
    for (int nt = 0; nt < 16; ++nt) {
        int col = nt * 8 + 2 * tig;
        *(float2*)&outb[ob + col] =
            make_float2(o[nt][0] * i0, o[nt][1] * i0);
        *(float2*)&outb[ob + (size_t)8 * INNER + col] =
            make_float2(o[nt][2] * i1, o[nt][3] * i1);
    }
}

// ---------------------------------------------------------------------------
// Entry point
// ---------------------------------------------------------------------------
extern "C" void kernel_launch(void* const* d_in, const int* in_sizes, int n_in,
                              void* d_out, int out_size)
{
    (void)out_size;
    const int NX = BB * TT * DIMM;
    const int NW = DIMM * NQKV;
    const int NO = INNER * DIMM;

    const float* x     = nullptr;
    const float* w_qkv = nullptr;
    const float* w_out = nullptr;
    for (int i = 0; i < n_in; ++i) {
        int sz = in_sizes[i];
        if      (sz == NX || sz == NX * 4) x     = (const float*)d_in[i];
        else if (sz == NW || sz == NW * 4) w_qkv = (const float*)d_in[i];
        else if (sz == NO || sz == NO * 4) w_out = (const float*)d_in[i];
    }
    if (!x || !w_qkv || !w_out) {
        x     = (const float*)d_in[0];
        w_qkv = (const float*)d_in[1];
        w_out = (const float*)d_in[2];
    }

    float* out = (float*)d_out;

    float *qkv_p, *attn_p;
    __half *ah, *bhp;
    __half *qh, *ql, *kh, *kl, *vt;
    cudaGetSymbolAddress((void**)&qkv_p,  g_qkv);
    cudaGetSymbolAddress((void**)&attn_p, g_attn);
    cudaGetSymbolAddress((void**)&ah,  gA_h);
    cudaGetSymbolAddress((void**)&bhp, gB_h);
    cudaGetSymbolAddress((void**)&qh, gQh);
    cudaGetSymbolAddress((void**)&ql, gQl);
    cudaGetSymbolAddress((void**)&kh, gKh);
    cudaGetSymbolAddress((void**)&kl, gKl);
    cudaGetSymbolAddress((void**)&vt, gVt);

    cudaFuncSetAttribute(gemm_fp16,
                         cudaFuncAttributeMaxDynamicSharedMemorySize, GEMM_SMEM);
    cudaFuncSetAttribute(attn_fa,
                         cudaFuncAttributeMaxDynamicSharedMemorySize, ATTN_SMEM);

    // 1. RoPE tables
    table_kernel<<<(TT * 64) / 256, 256>>>();

    // 2. GEMM operands; QKV projection (pure fp16, 1 MMA per sub-tile)
    conv_h<<<NX / 1024, 256>>>(x, ah);
    conv_T<<<dim3(NQKV / 32, DIMM / 32), dim3(32, 8)>>>(w_qkv, bhp, DIMM, NQKV);
    gemm_fp16<<<dim3(NQKV / 128, MROWS / 128), 256, GEMM_SMEM>>>(
        ah, bhp, qkv_p, DIMM, NQKV);

    // 3. RoPE + fp16 conversion for attention operands
    rope_conv<<<(MROWS * HEADS * 64) / 256, 256>>>(qkv_p, qh, ql, kh, kl);
    conv_vT<<<dim3(TT / 32, HD / 32, BB * HEADS), dim3(32, 8)>>>(qkv_p, vt);

    // 4. Tensor-core causal flash attention (hi/lo-split scores, unchanged)
    attn_fa<<<dim3(TT / 64, BB * HEADS), 128, ATTN_SMEM>>>(
        qh, ql, kh, kl, vt, attn_p);

    // 5. Out projection (pure fp16)
    conv_h<<<(MROWS * INNER) / 1024, 256>>>(attn_p, ah);
    conv_T<<<dim3(DIMM / 32, INNER / 32), dim3(32, 8)>>>(w_out, bhp, INNER, DIMM);
    gemm_fp16<<<dim3(DIMM / 128, MROWS / 128), 256, GEMM_SMEM>>>(
        ah, bhp, out, INNER, DIMM);
}

// round 17
// speedup vs baseline: 11.7291x; 1.1889x over previous
#include <cuda_runtime.h>
#include <cuda_fp16.h>
#include <math.h>
#include <stdint.h>

#define TT    2048
#define BB    2
#define DIMM  2048
#define HEADS 16
#define HD    128
#define INNER 2048
#define NQKV  6144
#define MROWS 4096   // B*T

// ---------------------------------------------------------------------------
// Scratch (device globals; no allocations allowed)
// ---------------------------------------------------------------------------
__device__ float g_qkv[(size_t)MROWS * NQKV];   // [4096, 6144] q|k|v (fp32)
__device__ float g_cos[TT * 64];
__device__ float g_sin[TT * 64];
// fp16 GEMM operand buffers
__device__ __half gA_h[(size_t)MROWS * DIMM];
__device__ __half gB_h[(size_t)NQKV * DIMM];    // [N,K] transposed
// fp16 attention operand buffers (hi/lo split kept for accuracy)
__device__ __half gQh[(size_t)MROWS * INNER];
__device__ __half gQl[(size_t)MROWS * INNER];
__device__ __half gKh[(size_t)MROWS * INNER];
__device__ __half gKl[(size_t)MROWS * INNER];
__device__ __half gVt[(size_t)BB * HEADS * HD * TT];  // [bh][d][t]

// ---------------------------------------------------------------------------
// Portable PTX helpers (sm_80+): cp.async + mma.sync fp16
// ---------------------------------------------------------------------------
__device__ __forceinline__ uint32_t smem_u32(const void* p) {
    uint32_t a;
    asm("{ .reg .u64 t; cvta.to.shared.u64 t, %1; cvt.u32.u64 %0, t; }"
        : "=r"(a) : "l"(p));
    return a;
}
__device__ __forceinline__ void cp16(uint32_t saddr, const void* g) {
    asm volatile("cp.async.ca.shared.global [%0], [%1], 16;"
                 :: "r"(saddr), "l"(g) : "memory");
}
#define CP_COMMIT() asm volatile("cp.async.commit_group;" ::: "memory")
#define CP_WAIT0()  asm volatile("cp.async.wait_group 0;" ::: "memory")
#define CP_WAIT1()  asm volatile("cp.async.wait_group 1;" ::: "memory")

__device__ __forceinline__ void mma16816(float* c, const uint32_t* a,
                                         const uint32_t* b) {
    asm volatile(
        "mma.sync.aligned.m16n8k16.row.col.f32.f16.f16.f32 "
        "{%0,%1,%2,%3}, {%4,%5,%6,%7}, {%8,%9}, {%0,%1,%2,%3};"
        : "+f"(c[0]), "+f"(c[1]), "+f"(c[2]), "+f"(c[3])
        : "r"(a[0]), "r"(a[1]), "r"(a[2]), "r"(a[3]), "r"(b[0]), "r"(b[1]));
}
__device__ __forceinline__ uint32_t packh2(float lo, float hi) {
    __half2 h = __floats2half2_rn(lo, hi);
    return *(uint32_t*)&h;
}

// ---------------------------------------------------------------------------
// RoPE cos/sin tables in fp64
// ---------------------------------------------------------------------------
__global__ void table_kernel() {
    int idx = blockIdx.x * 256 + threadIdx.x;
    int j = idx & 63;
    int t = idx >> 6;
    double inv = exp(-log(10000.0) * (double)j / 64.0);
    double ang = (double)t * inv;
    g_cos[idx] = (float)cos(ang);
    g_sin[idx] = (float)sin(ang);
}

// ---------------------------------------------------------------------------
// fp32 -> fp16 (GEMM A operand)
// ---------------------------------------------------------------------------
__global__ __launch_bounds__(256) void conv_h(
    const float* __restrict__ src, __half* __restrict__ dst)
{
    int i = blockIdx.x * 256 + threadIdx.x;
    float4 v = ((const float4*)src)[i];
    __half2 h0 = __floats2half2_rn(v.x, v.y);
    __half2 h1 = __floats2half2_rn(v.z, v.w);
    ((__half2*)dst)[i * 2]     = h0;
    ((__half2*)dst)[i * 2 + 1] = h1;
}

// ---------------------------------------------------------------------------
// fp32 [K,N] -> transposed single fp16 [N,K] (GEMM B operand)
// ---------------------------------------------------------------------------
__global__ __launch_bounds__(256) void conv_T(
    const float* __restrict__ src, __half* __restrict__ hiT, int K, int N)
{
    __shared__ float tile[32][33];
    int n0 = blockIdx.x * 32, k0 = blockIdx.y * 32;
    int tx = threadIdx.x, ty = threadIdx.y;
#pragma unroll
    for (int j = 0; j < 4; ++j)
        tile[ty + 8 * j][tx] = src[(size_t)(k0 + ty + 8 * j) * N + n0 + tx];
    __syncthreads();
#pragma unroll
    for (int j = 0; j < 4; ++j) {
        float v = tile[tx][ty + 8 * j];
        hiT[(size_t)(n0 + ty + 8 * j) * K + k0 + tx] = __float2half(v);
    }
}

// ---------------------------------------------------------------------------
// mma.sync pure-fp16 GEMM.  CTA: 128x128, 128 threads = 4 warps (2M x 2N),
// warp tile 64x64 -> 1.0 LDS per MMA.  2-stage cp.async, 2 CTAs/SM.
// ---------------------------------------------------------------------------
#define KC       32
#define ROWB     80
#define A_TILE_B (128 * ROWB)              // 10240
#define B_TILE_B (128 * ROWB)              // 10240
#define OFF_A    0
#define OFF_B    A_TILE_B
#define STAGE_B  (A_TILE_B + B_TILE_B)     // 20480
#define GEMM_SMEM (2 * STAGE_B)            // 40960

__device__ __forceinline__ void load_chunk(
    uint32_t sbase,
    const __half* __restrict__ Ah, const __half* __restrict__ Bh,
    int bm, int bn, int kc, int Kd, int tid)
{
    // A and B: 128 rows x 4 segs = 512 cp16 each, over 128 threads (4 each)
#pragma unroll
    for (int it = 0; it < 4; ++it) {
        int seg = it * 128 + tid;
        int r = seg >> 2, s = seg & 3;
        cp16(sbase + OFF_A + r * ROWB + s * 16,
             Ah + (size_t)(bm + r) * Kd + kc * KC + s * 8);
        cp16(sbase + OFF_B + r * ROWB + s * 16,
             Bh + (size_t)(bn + r) * Kd + kc * KC + s * 8);
    }
}

__global__ __launch_bounds__(128, 2) void gemm_fp16(
    const __half* __restrict__ Ah, const __half* __restrict__ Bh,
    float* __restrict__ C, int Kd, int Ncols)
{
    extern __shared__ char smem[];
    const uint32_t sb = smem_u32(smem);
    const int tid  = threadIdx.x;
    const int wid  = tid >> 5;
    const int lane = tid & 31;
    const int g    = lane >> 2;
    const int tig  = lane & 3;
    const int wm   = wid & 1;           // M offset 64*wm
    const int wn   = wid >> 1;          // N offset 64*wn
    const int bm   = blockIdx.y * 128;
    const int bn   = blockIdx.x * 128;

    float acc[4][8][4];
#pragma unroll
    for (int ms = 0; ms < 4; ++ms)
#pragma unroll
        for (int ns = 0; ns < 8; ++ns)
#pragma unroll
            for (int q = 0; q < 4; ++q) acc[ms][ns][q] = 0.0f;

    const int NT = Kd / KC;

    load_chunk(sb, Ah, Bh, bm, bn, 0, Kd, tid);
    CP_COMMIT();

    for (int kc = 0; kc < NT; ++kc) {
        const int cur = kc & 1;
        if (kc + 1 < NT) {
            load_chunk(sb + (cur ^ 1) * STAGE_B, Ah, Bh,
                       bm, bn, kc + 1, Kd, tid);
            CP_COMMIT();
            CP_WAIT1();
        } else {
            CP_WAIT0();
        }
        __syncthreads();

        const char* st = smem + cur * STAGE_B;
#pragma unroll
        for (int kk = 0; kk < 2; ++kk) {
            const int kbyte = kk * 32 + tig * 4;

            uint32_t af[4][4];
#pragma unroll
            for (int ms = 0; ms < 4; ++ms) {
                const char* ar = st + (wm * 64 + ms * 16 + g) * ROWB + kbyte;
                af[ms][0] = *(const uint32_t*)(ar + OFF_A);
                af[ms][1] = *(const uint32_t*)(ar + OFF_A + 8 * ROWB);
                af[ms][2] = *(const uint32_t*)(ar + OFF_A + 16);
                af[ms][3] = *(const uint32_t*)(ar + OFF_A + 8 * ROWB + 16);
            }
#pragma unroll
            for (int ns = 0; ns < 8; ++ns) {
                const char* br = st + (wn * 64 + ns * 8 + g) * ROWB + kbyte;
                uint32_t bf[2];
                bf[0] = *(const uint32_t*)(br + OFF_B);
                bf[1] = *(const uint32_t*)(br + OFF_B + 16);
#pragma unroll
                for (int ms = 0; ms < 4; ++ms)
                    mma16816(acc[ms][ns], af[ms], bf);
            }
        }
        __syncthreads();
    }

#pragma unroll
    for (int ms = 0; ms < 4; ++ms) {
        const int row = bm + wm * 64 + ms * 16 + g;
#pragma unroll
        for (int ns = 0; ns < 8; ++ns) {
            const int col = bn + wn * 64 + ns * 8 + tig * 2;
            *(float2*)&C[(size_t)row * Ncols + col] =
                make_float2(acc[ms][ns][0], acc[ms][ns][1]);
            *(float2*)&C[(size_t)(row + 8) * Ncols + col] =
                make_float2(acc[ms][ns][2], acc[ms][ns][3]);
        }
    }
}

// ---------------------------------------------------------------------------
// RoPE + fp16 split conversion for Q (pre-scaled) and K.
// ---------------------------------------------------------------------------
__global__ __launch_bounds__(256) void rope_conv(
    const float* __restrict__ qkv,
    __half* __restrict__ Qh, __half* __restrict__ Ql,
    __half* __restrict__ Kh, __half* __restrict__ Kl)
{
    int idx = blockIdx.x * 256 + threadIdx.x;   // < 4194304
    int j = idx & 63;
    int h = (idx >> 6) & 15;
    int m = idx >> 10;
    int t = m & (TT - 1);
    float c = g_cos[t * 64 + j];
    float s = g_sin[t * 64 + j];
    const float scale = 0.08838834764831845f;

    size_t ib = (size_t)m * NQKV + h * HD + j;
    float q1 = qkv[ib], q2 = qkv[ib + 64];
    float k1 = qkv[ib + INNER], k2 = qkv[ib + INNER + 64];
    float qa = (q1 * c - q2 * s) * scale;
    float qb = (q2 * c + q1 * s) * scale;
    float ka = k1 * c - k2 * s;
    float kb = k2 * c + k1 * s;

    size_t ob = (size_t)m * INNER + h * HD + j;
    __half hh;
    hh = __float2half(qa); Qh[ob] = hh;
    Ql[ob] = __float2half(qa - __half2float(hh));
    hh = __float2half(qb); Qh[ob + 64] = hh;
    Ql[ob + 64] = __float2half(qb - __half2float(hh));
    hh = __float2half(ka); Kh[ob] = hh;
    Kl[ob] = __float2half(ka - __half2float(hh));
    hh = __float2half(kb); Kh[ob + 64] = hh;
    Kl[ob + 64] = __float2half(kb - __half2float(hh));
}

// ---------------------------------------------------------------------------
// V: fp32 strided -> fp16 transposed [bh][d][t]
// ---------------------------------------------------------------------------
__global__ __launch_bounds__(256) void conv_vT(
    const float* __restrict__ qkv, __half* __restrict__ Vt)
{
    __shared__ float tile[32][33];
    int t0 = blockIdx.x * 32;
    int d0 = blockIdx.y * 32;
    int bh = blockIdx.z;
    int b = bh >> 4, h = bh & 15;
    int tx = threadIdx.x, ty = threadIdx.y;
    const float* src = qkv + (size_t)(b * TT) * NQKV + 2 * INNER + h * HD;
#pragma unroll
    for (int j = 0; j < 4; ++j)
        tile[ty + 8 * j][tx] = src[(size_t)(t0 + ty + 8 * j) * NQKV + d0 + tx];
    __syncthreads();
    __half* dst = Vt + (size_t)bh * HD * TT;
#pragma unroll
    for (int j = 0; j < 4; ++j)
        dst[(size_t)(d0 + ty + 8 * j) * TT + t0 + tx] =
            __float2half(tile[tx][ty + 8 * j]);
}

// ---------------------------------------------------------------------------
// Tensor-core causal flash attention (validated).
// Output written directly as fp16 into the out-proj A buffer.
// ---------------------------------------------------------------------------
#define QROWB 272
#define VROWB 144
#define SQH 0
#define SQL 17408
#define SKH 34816
#define SKL 52224
#define SVT 69632
#define ATTN_SMEM 88064

__global__ __launch_bounds__(128, 2) void attn_fa(
    const __half* __restrict__ Qh_, const __half* __restrict__ Ql_,
    const __half* __restrict__ Kh_, const __half* __restrict__ Kl_,
    const __half* __restrict__ Vt_, __half* __restrict__ outh)
{
    extern __shared__ char sm_[];
    const uint32_t sb = smem_u32(sm_);
    const char* smc = sm_;
    const int tid  = threadIdx.x;
    const int lane = tid & 31;
    const int w    = tid >> 5;
    const int g    = lane >> 2;
    const int tig  = lane & 3;
    const int qt   = (int)(gridDim.x - 1 - blockIdx.x);   // heavy first
    const int q0   = qt * 64;
    const int bh   = blockIdx.y;
    const int b    = bh >> 4;
    const int h    = bh & 15;

    const size_t qrow0 = (size_t)(b * TT + q0) * INNER + h * HD;
#pragma unroll
    for (int it = 0; it < 8; ++it) {
        int seg = it * 128 + tid;
        int r = seg >> 4, s2 = seg & 15;
        cp16(sb + SQH + r * QROWB + s2 * 16, Qh_ + qrow0 + (size_t)r * INNER + s2 * 8);
        cp16(sb + SQL + r * QROWB + s2 * 16, Ql_ + qrow0 + (size_t)r * INNER + s2 * 8);
    }
    CP_COMMIT();

    float o[16][4];
#pragma unroll
    for (int nt = 0; nt < 16; ++nt)
#pragma unroll
        for (int q = 0; q < 4; ++q) o[nt][q] = 0.0f;
    float m0 = -1.0e30f, m1 = -1.0e30f, l0 = 0.0f, l1 = 0.0f;

    for (int kb = 0; kb <= qt; ++kb) {
        const int k0 = kb * 64;
        const size_t krow0 = (size_t)(b * TT + k0) * INNER + h * HD;
        const size_t vrow0 = (size_t)bh * HD * TT + k0;
#pragma unroll
        for (int it = 0; it < 8; ++it) {
            int seg = it * 128 + tid;
            int r = seg >> 4, s2 = seg & 15;
            cp16(sb + SKH + r * QROWB + s2 * 16, Kh_ + krow0 + (size_t)r * INNER + s2 * 8);
            cp16(sb + SKL + r * QROWB + s2 * 16, Kl_ + krow0 + (size_t)r * INNER + s2 * 8);
            int d = seg >> 3, s3 = seg & 7;
            cp16(sb + SVT + d * VROWB + s3 * 16, Vt_ + vrow0 + (size_t)d * TT + s3 * 8);
        }
        CP_COMMIT();
        CP_WAIT0();
        __syncthreads();

        float sf[8][4];
#pragma unroll
        for (int ns = 0; ns < 8; ++ns)
#pragma unroll
            for (int q = 0; q < 4; ++q) sf[ns][q] = 0.0f;

#pragma unroll
        for (int ch = 0; ch < 8; ++ch) {
            const int kbyte = ch * 32 + tig * 4;
            const char* aq = smc + (w * 16 + g) * QROWB + kbyte;
            uint32_t ah4[4], al4[4];
            ah4[0] = *(const uint32_t*)(aq + SQH);
            ah4[1] = *(const uint32_t*)(aq + SQH + 8 * QROWB);
            ah4[2] = *(const uint32_t*)(aq + SQH + 16);
            ah4[3] = *(const uint32_t*)(aq + SQH + 8 * QROWB + 16);
            al4[0] = *(const uint32_t*)(aq + SQL);
            al4[1] = *(const uint32_t*)(aq + SQL + 8 * QROWB);
            al4[2] = *(const uint32_t*)(aq + SQL + 16);
            al4[3] = *(const uint32_t*)(aq + SQL + 8 * QROWB + 16);
#pragma unroll
            for (int ns = 0; ns < 8; ++ns) {
                const char* bk = smc + (ns * 8 + g) * QROWB + kbyte;
                uint32_t bh2[2], bl2[2];
                bh2[0] = *(const uint32_t*)(bk + SKH);
                bh2[1] = *(const uint32_t*)(bk + SKH + 16);
                bl2[0] = *(const uint32_t*)(bk + SKL);
                bl2[1] = *(const uint32_t*)(bk + SKL + 16);
                mma16816(sf[ns], ah4, bh2);
                mma16816(sf[ns], ah4, bl2);
                mma16816(sf[ns], al4, bh2);
            }
        }

        if (kb == qt) {
#pragma unroll
            for (int ns = 0; ns < 8; ++ns) {
                int cc = ns * 8 + 2 * tig;
                int rr = w * 16 + g;
                if (cc     > rr)     sf[ns][0] = -1.0e30f;
                if (cc + 1 > rr)     sf[ns][1] = -1.0e30f;
                if (cc     > rr + 8) sf[ns][2] = -1.0e30f;
                if (cc + 1 > rr + 8) sf[ns][3] = -1.0e30f;
            }
        }

        float rm0 = -1.0e30f, rm1 = -1.0e30f;
#pragma unroll
        for (int ns = 0; ns < 8; ++ns) {
            rm0 = fmaxf(rm0, fmaxf(sf[ns][0], sf[ns][1]));
            rm1 = fmaxf(rm1, fmaxf(sf[ns][2], sf[ns][3]));
        }
        rm0 = fmaxf(rm0, __shfl_xor_sync(0xffffffffu, rm0, 1));
        rm0 = fmaxf(rm0, __shfl_xor_sync(0xffffffffu, rm0, 2));
        rm1 = fmaxf(rm1, __shfl_xor_sync(0xffffffffu, rm1, 1));
        rm1 = fmaxf(rm1, __shfl_xor_sync(0xffffffffu, rm1, 2));
        float mn0 = fmaxf(m0, rm0), mn1 = fmaxf(m1, rm1);
        float a0 = __expf(m0 - mn0), a1 = __expf(m1 - mn1);
        m0 = mn0; m1 = mn1;

        float rs0 = 0.0f, rs1 = 0.0f;
#pragma unroll
        for (int ns = 0; ns < 8; ++ns) {
            sf[ns][0] = __expf(sf[ns][0] - mn0);
            sf[ns][1] = __expf(sf[ns][1] - mn0);
            sf[ns][2] = __expf(sf[ns][2] - mn1);
            sf[ns][3] = __expf(sf[ns][3] - mn1);
            rs0 += sf[ns][0] + sf[ns][1];
            rs1 += sf[ns][2] + sf[ns][3];
        }
        rs0 += __shfl_xor_sync(0xffffffffu, rs0, 1);
        rs0 += __shfl_xor_sync(0xffffffffu, rs0, 2);
        rs1 += __shfl_xor_sync(0xffffffffu, rs1, 1);
        rs1 += __shfl_xor_sync(0xffffffffu, rs1, 2);
        l0 = l0 * a0 + rs0;
        l1 = l1 * a1 + rs1;

#pragma unroll
        for (int nt = 0; nt < 16; ++nt) {
            o[nt][0] *= a0; o[nt][1] *= a0;
            o[nt][2] *= a1; o[nt][3] *= a1;
        }

        uint32_t pa[4][4];
#pragma unroll
        for (int j = 0; j < 4; ++j) {
            pa[j][0] = packh2(sf[2 * j][0],     sf[2 * j][1]);
            pa[j][1] = packh2(sf[2 * j][2],     sf[2 * j][3]);
            pa[j][2] = packh2(sf[2 * j + 1][0], sf[2 * j + 1][1]);
            pa[j][3] = packh2(sf[2 * j + 1][2], sf[2 * j + 1][3]);
        }

#pragma unroll
        for (int j = 0; j < 4; ++j) {
#pragma unroll
            for (int nt = 0; nt < 16; ++nt) {
                const char* bv = smc + SVT + (nt * 8 + g) * VROWB + j * 32 + tig * 4;
                uint32_t bv2[2];
                bv2[0] = *(const uint32_t*)(bv);
                bv2[1] = *(const uint32_t*)(bv + 16);
                mma16816(o[nt], pa[j], bv2);
            }
        }
        __syncthreads();
    }

    // normalize + write fp16 directly (out-proj A operand layout [m][2048])
    float i0 = 1.0f / l0, i1 = 1.0f / l1;
    const int r0 = q0 + w * 16 + g;
    const size_t ob = (size_t)(b * TT + r0) * INNER + h * HD;
#pragma unroll
    for (int nt = 0; nt < 16; ++nt) {
        int col = nt * 8 + 2 * tig;
        *(uint32_t*)&outh[ob + col] = packh2(o[nt][0] * i0, o[nt][1] * i0);
        *(uint32_t*)&outh[ob + (size_t)8 * INNER + col] =
            packh2(o[nt][2] * i1, o[nt][3] * i1);
    }
}

// ---------------------------------------------------------------------------
// Entry point
// ---------------------------------------------------------------------------
extern "C" void kernel_launch(void* const* d_in, const int* in_sizes, int n_in,
                              void* d_out, int out_size)
{
    (void)out_size;
    const int NX = BB * TT * DIMM;
    const int NW = DIMM * NQKV;
    const int NO = INNER * DIMM;

    const float* x     = nullptr;
    const float* w_qkv = nullptr;
    const float* w_out = nullptr;
    for (int i = 0; i < n_in; ++i) {
        int sz = in_sizes[i];
        if      (sz == NX || sz == NX * 4) x     = (const float*)d_in[i];
        else if (sz == NW || sz == NW * 4) w_qkv = (const float*)d_in[i];
        else if (sz == NO || sz == NO * 4) w_out = (const float*)d_in[i];
    }
    if (!x || !w_qkv || !w_out) {
        x     = (const float*)d_in[0];
        w_qkv = (const float*)d_in[1];
        w_out = (const float*)d_in[2];
    }

    float* out = (float*)d_out;

    float* qkv_p;
    __half *ah, *bhp;
    __half *qh, *ql, *kh, *kl, *vt;
    cudaGetSymbolAddress((void**)&qkv_p, g_qkv);
    cudaGetSymbolAddress((void**)&ah,  gA_h);
    cudaGetSymbolAddress((void**)&bhp, gB_h);
    cudaGetSymbolAddress((void**)&qh, gQh);
    cudaGetSymbolAddress((void**)&ql, gQl);
    cudaGetSymbolAddress((void**)&kh, gKh);
    cudaGetSymbolAddress((void**)&kl, gKl);
    cudaGetSymbolAddress((void**)&vt, gVt);

    cudaFuncSetAttribute(gemm_fp16,
                         cudaFuncAttributeMaxDynamicSharedMemorySize, GEMM_SMEM);
    cudaFuncSetAttribute(attn_fa,
                         cudaFuncAttributeMaxDynamicSharedMemorySize, ATTN_SMEM);

    // 1. RoPE tables
    table_kernel<<<(TT * 64) / 256, 256>>>();

    // 2. GEMM operands; QKV projection (CTA 128x128, warp 64x64)
    conv_h<<<NX / 1024, 256>>>(x, ah);
    conv_T<<<dim3(NQKV / 32, DIMM / 32), dim3(32, 8)>>>(w_qkv, bhp, DIMM, NQKV);
    gemm_fp16<<<dim3(NQKV / 128, MROWS / 128), 128, GEMM_SMEM>>>(
        ah, bhp, qkv_p, DIMM, NQKV);

    // 3. RoPE + fp16 conversion for attention operands
    rope_conv<<<(MROWS * HEADS * 64) / 256, 256>>>(qkv_p, qh, ql, kh, kl);
    conv_vT<<<dim3(TT / 32, HD / 32, BB * HEADS), dim3(32, 8)>>>(qkv_p, vt);

    // 4. Tensor-core causal flash attention -> writes fp16 A buffer directly
    attn_fa<<<dim3(TT / 64, BB * HEADS), 128, ATTN_SMEM>>>(
        qh, ql, kh, kl, vt, ah);

    // 5. Out projection
    conv_T<<<dim3(DIMM / 32, INNER / 32), dim3(32, 8)>>>(w_out, bhp, INNER, DIMM);
    gemm_fp16<<<dim3(DIMM / 128, MROWS / 128), 128, GEMM_SMEM>>>(
        ah, bhp, out, INNER, DIMM);
}